// round 1
// baseline (speedup 1.0000x reference)
#include <cuda_runtime.h>
#include <math.h>

// ---------------- problem constants ----------------
#define BB   8
#define CIN  3
#define H0   256
#define W0   256
#define CH   64
#define MIDC 32
#define NL   4
#define HP   264
#define WP   264
#define NKY  32      // kept rfft column modes
#define NKX  64      // kept row freqs: {0..31} U {232..263}
#define MM   32      // weight mode dim

// ---------------- scratch (static device globals; no allocation) ----------------
__device__ __align__(16) float g_hA[(size_t)BB*CH*HP*WP];        // 142.7 MB
__device__ __align__(16) float g_hB[(size_t)BB*CH*HP*WP];        // 142.7 MB
__device__ __align__(16) float g_X [(size_t)BB*CH*HP*NKY*2];     // W-DFT out   34.6 MB
__device__ __align__(16) float g_Z [(size_t)BB*CH*NKX*NKY*2];    // H-DFT out   16.8 MB
__device__ __align__(16) float g_Yv[(size_t)BB*CH*NKX*NKY*2];    // mode-mix out
__device__ __align__(16) float g_Z2[(size_t)BB*CH*HP*NKY*2];     // inv-H out   34.6 MB

// DFT bases (rebuilt every call; deterministic)
__device__ float g_FwC[WP*NKY], g_FwS[WP*NKY];  // [w][ky]  (S holds -sin)
__device__ float g_EHc[NKX*HP], g_EHs[NKX*HP];  // [kx][h]  forward H twiddles
__device__ float g_IHc[HP*NKX], g_IHs[HP*NKX];  // [h][kx]  inverse H, scaled 1/HP
__device__ float g_IWc[NKY*WP], g_IWs[NKY*WP];  // [ky][w]  inverse W, scaled wgt/WP

__device__ __forceinline__ float gelu_exact(float v) {
    return 0.5f * v * (1.0f + erff(v * 0.70710678118654752f));
}

// ---------------- basis init ----------------
__global__ void k_init_basis() {
    int idx = blockIdx.x * blockDim.x + threadIdx.x;
    const double PI2 = 6.283185307179586476925286766559;
    if (idx < WP*NKY) {            // forward W basis
        int w = idx / NKY, ky = idx % NKY;
        int m = (w * ky) % WP;
        double th = PI2 * (double)m / (double)WP;
        g_FwC[idx] = (float)cos(th);
        g_FwS[idx] = (float)(-sin(th));
    }
    if (idx < NKX*HP) {            // forward H twiddles e^{-i th}: handled in kernel
        int kx = idx / HP, h = idx % HP;
        int kxv = (kx < 32) ? kx : kx + 200;      // 232..263
        int m = (kxv * h) % HP;
        double th = PI2 * (double)m / (double)HP;
        g_EHc[idx] = (float)cos(th);
        g_EHs[idx] = (float)sin(th);
    }
    if (idx < HP*NKX) {            // inverse H, e^{+i th}/HP
        int h = idx / NKX, kx = idx % NKX;
        int kxv = (kx < 32) ? kx : kx + 200;
        int m = (kxv * h) % HP;
        double th = PI2 * (double)m / (double)HP;
        g_IHc[idx] = (float)(cos(th) / (double)HP);
        g_IHs[idx] = (float)(sin(th) / (double)HP);
    }
    if (idx < NKY*WP) {            // inverse W (c2r): wgt * cos/sin / WP
        int ky = idx / WP, w = idx % WP;
        int m = (ky * w) % WP;
        double th = PI2 * (double)m / (double)WP;
        double wgt = ((ky == 0) ? 1.0 : 2.0) / (double)WP;
        g_IWc[idx] = (float)(wgt * cos(th));
        g_IWs[idx] = (float)(wgt * sin(th));
    }
}

// ---------------- lift: [x;coords] -> gelu(W1) -> W2, write padded h ----------------
__global__ void k_lift(const float* __restrict__ x,
                       const float* __restrict__ w1, const float* __restrict__ b1,
                       const float* __restrict__ w2, const float* __restrict__ b2,
                       float* __restrict__ hout) {
    int h = blockIdx.x, b = blockIdx.y;
    for (int w = threadIdx.x; w < WP; w += blockDim.x) {
        size_t base = ((size_t)b*CH)*HP*WP + (size_t)h*WP + (size_t)w;
        if (h >= H0 || w >= W0) {
            for (int o = 0; o < CH; o++) hout[base + (size_t)o*HP*WP] = 0.0f;
            continue;
        }
        float in5[5];
        #pragma unroll
        for (int c = 0; c < CIN; c++)
            in5[c] = x[(((size_t)b*CIN + c)*H0 + h)*W0 + w];
        in5[3] = (float)h * (1.0f/255.0f);
        in5[4] = (float)w * (1.0f/255.0f);
        float mid[MIDC];
        #pragma unroll
        for (int m = 0; m < MIDC; m++) {
            float s = b1[m];
            #pragma unroll
            for (int i = 0; i < 5; i++) s += w1[m*5 + i] * in5[i];
            mid[m] = gelu_exact(s);
        }
        #pragma unroll 8
        for (int o = 0; o < CH; o++) {
            float s = b2[o];
            #pragma unroll
            for (int m = 0; m < MIDC; m++) s += w2[o*MIDC + m] * mid[m];
            hout[base + (size_t)o*HP*WP] = s;
        }
    }
}

// ---------------- K1: partial rDFT along W. rows = B*CH*HP, [264] -> [32] complex --------
__global__ void k_dftw(const float* __restrict__ hin) {
    int r0 = blockIdx.x * 64;
    int ky = threadIdx.x & 31;
    int rg = threadIdx.x >> 5;   // 0..7
    __shared__ float As[64][33];
    __shared__ float Bc[32][33], Bs[32][33];   // [ww][ky]
    float accR[8], accI[8];
    #pragma unroll
    for (int j = 0; j < 8; j++) { accR[j] = 0.f; accI[j] = 0.f; }

    for (int wt = 0; wt < 9; wt++) {
        int w0 = wt * 32;
        for (int t = threadIdx.x; t < 64*32; t += 256) {
            int rr = t >> 5, ww = t & 31;
            int w = w0 + ww;
            As[rr][ww] = (w < WP) ? hin[(size_t)(r0 + rr)*WP + w] : 0.f;
        }
        for (int t = threadIdx.x; t < 32*32; t += 256) {
            int ww = t >> 5, kk = t & 31;
            int w = w0 + ww;
            Bc[ww][kk] = (w < WP) ? g_FwC[w*NKY + kk] : 0.f;
            Bs[ww][kk] = (w < WP) ? g_FwS[w*NKY + kk] : 0.f;
        }
        __syncthreads();
        #pragma unroll
        for (int ww = 0; ww < 32; ww++) {
            float c = Bc[ww][ky], s = Bs[ww][ky];
            #pragma unroll
            for (int j = 0; j < 8; j++) {
                float a = As[rg*8 + j][ww];
                accR[j] += a * c;
                accI[j] += a * s;      // s already holds -sin
            }
        }
        __syncthreads();
    }
    #pragma unroll
    for (int j = 0; j < 8; j++) {
        size_t row = (size_t)r0 + rg*8 + j;
        ((float2*)g_X)[row*NKY + ky] = make_float2(accR[j], accI[j]);
    }
}

// ---------------- K2: complex DFT along H: per (b,c), [264,32] -> [64,32] ----------------
__global__ void k_dfth() {
    int bc = blockIdx.x;                 // 0..511
    int ky = threadIdx.x & 31;
    int kg = threadIdx.x >> 5;           // 0..7
    __shared__ float Xr[32][33], Xi[32][33];   // [hh][ky]
    __shared__ float Ec[64][32], Es[64][32];   // [kx][hh]
    float zr[8], zi[8];
    #pragma unroll
    for (int j = 0; j < 8; j++) { zr[j] = 0.f; zi[j] = 0.f; }
    const float2* Xb = ((const float2*)g_X) + (size_t)bc*HP*NKY;

    for (int ht = 0; ht < 9; ht++) {
        int h0 = ht * 32;
        for (int t = threadIdx.x; t < 32*32; t += 256) {
            int hh = t >> 5, kk = t & 31;
            int h = h0 + hh;
            float2 v = (h < HP) ? Xb[(size_t)h*NKY + kk] : make_float2(0.f, 0.f);
            Xr[hh][kk] = v.x; Xi[hh][kk] = v.y;
        }
        for (int t = threadIdx.x; t < 64*32; t += 256) {
            int kx = t >> 5, hh = t & 31;
            int h = h0 + hh;
            Ec[kx][hh] = (h < HP) ? g_EHc[kx*HP + h] : 0.f;
            Es[kx][hh] = (h < HP) ? g_EHs[kx*HP + h] : 0.f;
        }
        __syncthreads();
        #pragma unroll 8
        for (int hh = 0; hh < 32; hh++) {
            float xr = Xr[hh][ky], xi = Xi[hh][ky];
            #pragma unroll
            for (int j = 0; j < 8; j++) {
                int kx = kg*8 + j;
                float c = Ec[kx][hh], s = Es[kx][hh];
                zr[j] += xr*c + xi*s;     // e^{-i th}
                zi[j] += xi*c - xr*s;
            }
        }
        __syncthreads();
    }
    #pragma unroll
    for (int j = 0; j < 8; j++) {
        int kx = kg*8 + j;
        ((float2*)g_Z)[((size_t)bc*NKX + kx)*NKY + ky] = make_float2(zr[j], zi[j]);
    }
}

// ---------------- K3: per-mode complex 64x64 channel mixing ----------------
__global__ void k_modes(const float* __restrict__ spw1, const float* __restrict__ spw2) {
    int kx = blockIdx.x;       // 0..63
    int og = blockIdx.y;       // 0..7  (8 output channels each)
    int ky = threadIdx.x & 31;
    int b  = threadIdx.x >> 5; // 0..7
    const float* W; int mx;
    if (kx < 32) { W = spw1; mx = kx; } else { W = spw2; mx = kx - 32; }

    float yr[8], yi[8];
    #pragma unroll
    for (int oo = 0; oo < 8; oo++) { yr[oo] = 0.f; yi[oo] = 0.f; }

    for (int i = 0; i < CH; i++) {
        float2 z = ((const float2*)g_Z)[((size_t)(b*CH + i)*NKX + kx)*NKY + ky];
        #pragma unroll
        for (int oo = 0; oo < 8; oo++) {
            int o = og*8 + oo;
            float2 wv = ((const float2*)W)[(((size_t)i*CH + o)*MM + mx)*MM + ky];
            yr[oo] += z.x*wv.x - z.y*wv.y;
            yi[oo] += z.x*wv.y + z.y*wv.x;
        }
    }
    #pragma unroll
    for (int oo = 0; oo < 8; oo++) {
        int o = og*8 + oo;
        ((float2*)g_Yv)[((size_t)(b*CH + o)*NKX + kx)*NKY + ky] = make_float2(yr[oo], yi[oo]);
    }
}

// ---------------- K4: inverse DFT along H: per (b,o), [64,32] -> [264,32] ----------------
__global__ void k_idfth() {
    int bo = blockIdx.x;       // 0..511
    int ht = blockIdx.y;       // 0..8 (h tiles of 32)
    int ky = threadIdx.x & 31;
    int hg = threadIdx.x >> 5; // 0..7
    __shared__ float Yr[64][32], Yi[64][32];   // [kx][ky]
    __shared__ float Ic[32][64], Is[32][64];   // [hh][kx]
    const float2* Yb = ((const float2*)g_Yv) + (size_t)bo*NKX*NKY;

    for (int t = threadIdx.x; t < 64*32; t += 256) {
        int kx = t >> 5, kk = t & 31;
        float2 v = Yb[(size_t)kx*NKY + kk];
        Yr[kx][kk] = v.x; Yi[kx][kk] = v.y;
    }
    int h0 = ht * 32;
    for (int t = threadIdx.x; t < 32*64; t += 256) {
        int hh = t >> 6, kx = t & 63;
        int h = h0 + hh;
        Ic[hh][kx] = (h < HP) ? g_IHc[h*NKX + kx] : 0.f;
        Is[hh][kx] = (h < HP) ? g_IHs[h*NKX + kx] : 0.f;
    }
    __syncthreads();
    #pragma unroll
    for (int j = 0; j < 4; j++) {
        int hh = hg*4 + j;
        int h = h0 + hh;
        if (h < HP) {
            float ar = 0.f, ai = 0.f;
            #pragma unroll 8
            for (int kx = 0; kx < 64; kx++) {
                float c = Ic[hh][kx], s = Is[hh][kx];
                float yr = Yr[kx][ky], yi = Yi[kx][ky];
                ar += yr*c - yi*s;       // e^{+i th}
                ai += yr*s + yi*c;
            }
            ((float2*)g_Z2)[((size_t)bo*HP + h)*NKY + ky] = make_float2(ar, ai);
        }
    }
}

// ---------------- K5: fused inverse-W (c2r) + 1x1 conv + bias + gelu ----------------
// grid: (5 w-tiles of 64, HP, BB); 256 threads; dynamic smem 64KB
__global__ void k_layer_out(const float* __restrict__ hin,
                            const float* __restrict__ cw, const float* __restrict__ cb,
                            float* __restrict__ hout, int apply_gelu) {
    extern __shared__ float sm[];
    float* Hs = sm;               // [i=64][ww=64]
    float* Cs = sm + 4096;        // [o=64][i=64]  (same layout as conv_w)
    float* Zr = sm + 8192;        // [o=64][ky=32]
    float* Zi = sm + 10240;
    float* Wc = sm + 12288;       // [ky=32][ww=64]
    float* Ws = sm + 14336;

    int b = blockIdx.z, h = blockIdx.y, wt = blockIdx.x;
    int w0 = wt * 64;
    int tid = threadIdx.x;

    for (int t = tid; t < 4096; t += 256) {
        int i = t >> 6, ww = t & 63;
        int w = w0 + ww;
        Hs[t] = (w < WP) ? hin[((size_t)(b*CH + i)*HP + h)*WP + w] : 0.f;
        Cs[t] = cw[t];
    }
    for (int t = tid; t < 2048; t += 256) {
        int o  = t >> 5, kk = t & 31;
        float2 v = ((const float2*)g_Z2)[((size_t)(b*CH + o)*HP + h)*NKY + kk];
        Zr[t] = v.x; Zi[t] = v.y;
        int kyy = t >> 6, ww = t & 63;
        int w = w0 + ww;
        Wc[t] = (w < WP) ? g_IWc[kyy*WP + w] : 0.f;
        Ws[t] = (w < WP) ? g_IWs[kyy*WP + w] : 0.f;
    }
    __syncthreads();

    int wq = tid & 15;       // w quad: w = w0 + wq*4 + {0..3}
    int og = tid >> 4;       // o = og*4 + {0..3}
    float4 acc[4];
    #pragma unroll
    for (int oo = 0; oo < 4; oo++) {
        float bv = cb[og*4 + oo];
        acc[oo] = make_float4(bv, bv, bv, bv);
    }
    const float4* Hs4 = (const float4*)Hs;
    #pragma unroll 4
    for (int i = 0; i < 64; i++) {
        float4 hv = Hs4[i*16 + wq];
        #pragma unroll
        for (int oo = 0; oo < 4; oo++) {
            float a = Cs[(og*4 + oo)*64 + i];
            acc[oo].x += a*hv.x; acc[oo].y += a*hv.y;
            acc[oo].z += a*hv.z; acc[oo].w += a*hv.w;
        }
    }
    const float4* Wc4 = (const float4*)Wc;
    const float4* Ws4 = (const float4*)Ws;
    #pragma unroll 4
    for (int k2 = 0; k2 < 32; k2++) {
        float4 cv = Wc4[k2*16 + wq];
        float4 sv = Ws4[k2*16 + wq];
        #pragma unroll
        for (int oo = 0; oo < 4; oo++) {
            float zr = Zr[(og*4 + oo)*32 + k2];
            float zi = Zi[(og*4 + oo)*32 + k2];
            acc[oo].x += zr*cv.x - zi*sv.x;
            acc[oo].y += zr*cv.y - zi*sv.y;
            acc[oo].z += zr*cv.z - zi*sv.z;
            acc[oo].w += zr*cv.w - zi*sv.w;
        }
    }
    int w = w0 + wq*4;
    if (w < WP) {
        #pragma unroll
        for (int oo = 0; oo < 4; oo++) {
            float4 v = acc[oo];
            if (apply_gelu) {
                v.x = gelu_exact(v.x); v.y = gelu_exact(v.y);
                v.z = gelu_exact(v.z); v.w = gelu_exact(v.w);
            }
            int o = og*4 + oo;
            size_t idx = ((size_t)(b*CH + o)*HP + h)*WP + w;
            *((float4*)(hout + idx)) = v;
        }
    }
}

// ---------------- crop to output ----------------
__global__ void k_crop(const float* __restrict__ hin, float* __restrict__ out) {
    size_t idx = (size_t)blockIdx.x * blockDim.x + threadIdx.x;
    if (idx >= (size_t)BB*CH*H0*W0) return;
    int w  = (int)(idx & 255);
    int h  = (int)((idx >> 8) & 255);
    int bc = (int)(idx >> 16);
    out[idx] = hin[((size_t)bc*HP + h)*WP + w];
}

// ---------------- host launcher ----------------
extern "C" void kernel_launch(void* const* d_in, const int* in_sizes, int n_in,
                              void* d_out, int out_size) {
    const float* x       = (const float*)d_in[0];
    const float* lift_w1 = (const float*)d_in[1];
    const float* lift_b1 = (const float*)d_in[2];
    const float* lift_w2 = (const float*)d_in[3];
    const float* lift_b2 = (const float*)d_in[4];
    const float* conv_w  = (const float*)d_in[5];
    const float* conv_b  = (const float*)d_in[6];
    const float* spw1    = (const float*)d_in[7];
    const float* spw2    = (const float*)d_in[8];
    float* out = (float*)d_out;

    float *hA, *hB;
    cudaGetSymbolAddress((void**)&hA, g_hA);
    cudaGetSymbolAddress((void**)&hB, g_hB);

    cudaFuncSetAttribute(k_layer_out, cudaFuncAttributeMaxDynamicSharedMemorySize, 65536);

    k_init_basis<<<(NKX*HP + 255)/256, 256>>>();
    k_lift<<<dim3(HP, BB), 256>>>(x, lift_w1, lift_b1, lift_w2, lift_b2, hA);

    const size_t sp_stride = (size_t)CH*CH*MM*MM*2;   // per-layer spectral weights
    for (int l = 0; l < NL; l++) {
        const float* hin  = (l & 1) ? hB : hA;
        float*       hnxt = (l & 1) ? hA : hB;
        k_dftw<<<(BB*CH*HP)/64, 256>>>(hin);
        k_dfth<<<BB*CH, 256>>>();
        k_modes<<<dim3(NKX, 8), 256>>>(spw1 + (size_t)l*sp_stride,
                                       spw2 + (size_t)l*sp_stride);
        k_idfth<<<dim3(BB*CH, 9), 256>>>();
        k_layer_out<<<dim3(5, HP, BB), 256, 65536>>>(hin,
                                                     conv_w + (size_t)l*CH*CH,
                                                     conv_b + (size_t)l*CH,
                                                     hnxt, (l < NL-1) ? 1 : 0);
    }
    // after 4 layers the result is back in hA
    k_crop<<<(int)(((size_t)BB*CH*H0*W0 + 255)/256), 256>>>(hA, out);
}

// round 3
// speedup vs baseline: 1.2195x; 1.2195x over previous
#include <cuda_runtime.h>
#include <math.h>
#include <stdint.h>

// ---------------- problem constants ----------------
#define BB   8
#define CIN  3
#define H0   256
#define W0   256
#define CH   64
#define MIDC 32
#define NL   4
#define HP   264
#define WP   264
#define NKY  32
#define NKX  64
#define MM   32
#define HW   (HP*WP)          // 69696
#define MROWS (BB*CH*HP)      // 135168

// ---------------- scratch ----------------
__device__ __align__(16) float g_hA[(size_t)BB*CH*HP*WP];
__device__ __align__(16) float g_hB[(size_t)BB*CH*HP*WP];
__device__ __align__(16) float g_hC[(size_t)BB*CH*HP*WP];        // C1 (invW result)
__device__ __align__(16) float g_X [(size_t)BB*CH*HP*NKY*2];
__device__ __align__(16) float g_Z [(size_t)BB*CH*NKX*NKY*2];
__device__ __align__(16) float g_Yv[(size_t)BB*CH*NKX*NKY*2];
__device__ __align__(16) float g_Z2[(size_t)BB*CH*HP*NKY*2];

__device__ float g_FwC[WP*NKY], g_FwS[WP*NKY];  // [w][ky]  (S holds -sin)
__device__ float g_EHc[NKX*HP], g_EHs[NKX*HP];  // [kx][h]
__device__ float g_IHc[HP*NKX], g_IHs[HP*NKX];  // [h][kx]  scaled 1/HP
__device__ float g_IWc[NKY*WP], g_IWs[NKY*WP];  // [ky][w]  scaled wgt/WP

__device__ __forceinline__ float gelu_exact(float v) {
    return 0.5f * v * (1.0f + erff(v * 0.70710678118654752f));
}
__device__ __forceinline__ float to_tf32(float x) {
    uint32_t u; asm("cvt.rna.tf32.f32 %0, %1;" : "=r"(u) : "f"(x));
    return __uint_as_float(u);
}
__device__ __forceinline__ void mma_tf32(float c[4], uint32_t a0, uint32_t a1,
                                         uint32_t a2, uint32_t a3,
                                         uint32_t b0, uint32_t b1) {
    asm volatile("mma.sync.aligned.m16n8k8.row.col.f32.tf32.tf32.f32 "
                 "{%0,%1,%2,%3},{%4,%5,%6,%7},{%8,%9},{%0,%1,%2,%3};"
                 : "+f"(c[0]), "+f"(c[1]), "+f"(c[2]), "+f"(c[3])
                 : "r"(a0), "r"(a1), "r"(a2), "r"(a3), "r"(b0), "r"(b1));
}

// ---------------- basis init ----------------
__global__ void k_init_basis() {
    int idx = blockIdx.x * blockDim.x + threadIdx.x;
    const double PI2 = 6.283185307179586476925286766559;
    if (idx < WP*NKY) {
        int w = idx / NKY, ky = idx % NKY;
        int m = (w * ky) % WP;
        double th = PI2 * (double)m / (double)WP;
        g_FwC[idx] = (float)cos(th);
        g_FwS[idx] = (float)(-sin(th));
    }
    if (idx < NKX*HP) {
        int kx = idx / HP, h = idx % HP;
        int kxv = (kx < 32) ? kx : kx + 200;
        int m = (kxv * h) % HP;
        double th = PI2 * (double)m / (double)HP;
        g_EHc[idx] = (float)cos(th);
        g_EHs[idx] = (float)sin(th);
    }
    if (idx < HP*NKX) {
        int h = idx / NKX, kx = idx % NKX;
        int kxv = (kx < 32) ? kx : kx + 200;
        int m = (kxv * h) % HP;
        double th = PI2 * (double)m / (double)HP;
        g_IHc[idx] = (float)(cos(th) / (double)HP);
        g_IHs[idx] = (float)(sin(th) / (double)HP);
    }
    if (idx < NKY*WP) {
        int ky = idx / WP, w = idx % WP;
        int m = (ky * w) % WP;
        double th = PI2 * (double)m / (double)WP;
        double wgt = ((ky == 0) ? 1.0 : 2.0) / (double)WP;
        g_IWc[idx] = (float)(wgt * cos(th));
        g_IWs[idx] = (float)(wgt * sin(th));
    }
}

// ---------------- lift ----------------
__global__ void k_lift(const float* __restrict__ x,
                       const float* __restrict__ w1, const float* __restrict__ b1,
                       const float* __restrict__ w2, const float* __restrict__ b2,
                       float* __restrict__ hout) {
    int h = blockIdx.x, b = blockIdx.y;
    for (int w = threadIdx.x; w < WP; w += blockDim.x) {
        size_t base = ((size_t)b*CH)*HP*WP + (size_t)h*WP + (size_t)w;
        if (h >= H0 || w >= W0) {
            for (int o = 0; o < CH; o++) hout[base + (size_t)o*HP*WP] = 0.0f;
            continue;
        }
        float in5[5];
        #pragma unroll
        for (int c = 0; c < CIN; c++)
            in5[c] = x[(((size_t)b*CIN + c)*H0 + h)*W0 + w];
        in5[3] = (float)h * (1.0f/255.0f);
        in5[4] = (float)w * (1.0f/255.0f);
        float mid[MIDC];
        #pragma unroll
        for (int m = 0; m < MIDC; m++) {
            float s = b1[m];
            #pragma unroll
            for (int i = 0; i < 5; i++) s += w1[m*5 + i] * in5[i];
            mid[m] = gelu_exact(s);
        }
        #pragma unroll 8
        for (int o = 0; o < CH; o++) {
            float s = b2[o];
            #pragma unroll
            for (int m = 0; m < MIDC; m++) s += w2[o*MIDC + m] * mid[m];
            hout[base + (size_t)o*HP*WP] = s;
        }
    }
}

// ============ K1: W-rDFT as GEMM  C[135168,64] = hin[135168,264] x Wb[264,64] ============
__global__ void k1_dftw(const float* __restrict__ hin) {
    __shared__ float AS[128*25];   // [r][k] stride 25
    __shared__ float BS[64*25];    // [n][k] stride 25
    int tid = threadIdx.x;
    int warp = tid >> 5, lane = tid & 31;
    int g = lane >> 2, t = lane & 3;
    size_t row0 = (size_t)blockIdx.x * 128;
    float c[8][4];
    #pragma unroll
    for (int i = 0; i < 8; i++) { c[i][0]=0.f; c[i][1]=0.f; c[i][2]=0.f; c[i][3]=0.f; }

    for (int ch = 0; ch < 11; ch++) {
        int k0c = ch * 24;
        for (int i = tid; i < 128*24; i += 256) {
            int r = i / 24, kk = i % 24;
            AS[r*25 + kk] = to_tf32(hin[(row0 + r)*264 + k0c + kk]);
        }
        for (int i = tid; i < 64*24; i += 256) {
            int n = i / 24, kk = i % 24;
            int w = k0c + kk, ky = n >> 1;
            float v = (n & 1) ? g_FwS[w*NKY + ky] : g_FwC[w*NKY + ky];
            BS[n*25 + kk] = to_tf32(v);
        }
        __syncthreads();
        #pragma unroll
        for (int ks = 0; ks < 3; ks++) {
            int k0 = ks * 8;
            const float* Ar = &AS[(warp*16 + g)*25 + k0 + t];
            uint32_t a0 = __float_as_uint(Ar[0]);
            uint32_t a1 = __float_as_uint(Ar[8*25]);
            uint32_t a2 = __float_as_uint(Ar[4]);
            uint32_t a3 = __float_as_uint(Ar[8*25 + 4]);
            #pragma unroll
            for (int nt = 0; nt < 8; nt++) {
                uint32_t b0 = __float_as_uint(BS[(nt*8 + g)*25 + k0 + t]);
                uint32_t b1 = __float_as_uint(BS[(nt*8 + g)*25 + k0 + t + 4]);
                mma_tf32(c[nt], a0, a1, a2, a3, b0, b1);
            }
        }
        __syncthreads();
    }
    size_t r0 = row0 + warp*16 + g;
    #pragma unroll
    for (int nt = 0; nt < 8; nt++) {
        int n0 = nt*8 + 2*t;
        *(float2*)&g_X[r0*64 + n0]     = make_float2(c[nt][0], c[nt][1]);
        *(float2*)&g_X[(r0+8)*64 + n0] = make_float2(c[nt][2], c[nt][3]);
    }
}

// ============ K2: H-DFT as GEMM  per bc: C[128,32] = Estack[128,528] x Xstack[528,32] =====
__global__ void k2_dfth() {
    __shared__ float ES[128*25];
    __shared__ float XS[32*25];
    int tid = threadIdx.x;
    int warp = tid >> 5, lane = tid & 31;
    int g = lane >> 2, t = lane & 3;
    int bc = blockIdx.x;
    float c[4][4];
    #pragma unroll
    for (int i = 0; i < 4; i++) { c[i][0]=0.f; c[i][1]=0.f; c[i][2]=0.f; c[i][3]=0.f; }

    for (int ch = 0; ch < 22; ch++) {
        int k0c = ch * 24;
        for (int i = tid; i < 128*24; i += 256) {
            int r = i / 24, kk = i % 24;
            int k = k0c + kk;
            int kx = r & 63;
            float v;
            if (k < 264) {
                v = (r < 64) ?  g_EHc[kx*HP + k] : -g_EHs[kx*HP + k];
            } else {
                int h = k - 264;
                v = (r < 64) ?  g_EHs[kx*HP + h] :  g_EHc[kx*HP + h];
            }
            ES[r*25 + kk] = to_tf32(v);
        }
        for (int i = tid; i < 32*24; i += 256) {
            int kk = i >> 5, ky = i & 31;
            int k = k0c + kk;
            int hh = (k < 264) ? k : k - 264;
            float2 z = ((const float2*)g_X)[((size_t)bc*HP + hh)*NKY + ky];
            XS[ky*25 + kk] = to_tf32((k < 264) ? z.x : z.y);
        }
        __syncthreads();
        #pragma unroll
        for (int ks = 0; ks < 3; ks++) {
            int k0 = ks * 8;
            const float* Ar = &ES[(warp*16 + g)*25 + k0 + t];
            uint32_t a0 = __float_as_uint(Ar[0]);
            uint32_t a1 = __float_as_uint(Ar[8*25]);
            uint32_t a2 = __float_as_uint(Ar[4]);
            uint32_t a3 = __float_as_uint(Ar[8*25 + 4]);
            #pragma unroll
            for (int nt = 0; nt < 4; nt++) {
                uint32_t b0 = __float_as_uint(XS[(nt*8 + g)*25 + k0 + t]);
                uint32_t b1 = __float_as_uint(XS[(nt*8 + g)*25 + k0 + t + 4]);
                mma_tf32(c[nt], a0, a1, a2, a3, b0, b1);
            }
        }
        __syncthreads();
    }
    int r1 = warp*16 + g;
    #pragma unroll
    for (int nt = 0; nt < 4; nt++) {
        int col = nt*8 + 2*t;
        #pragma unroll
        for (int q = 0; q < 4; q++) {
            int r = r1 + (q >> 1)*8;
            int cc = col + (q & 1);
            int kx = r & 63;
            float* p = (float*)(((float2*)g_Z) + ((size_t)bc*NKX + kx)*NKY + cc);
            p[(r >> 6) & 1] = c[nt][q];
        }
    }
}

// ============ K3: per-mode complex 64x64 channel mixing (fp32) ============
__global__ void k_modes(const float* __restrict__ spw1, const float* __restrict__ spw2) {
    int kx = blockIdx.x;
    int og = blockIdx.y;
    int ky = threadIdx.x & 31;
    int b  = threadIdx.x >> 5;
    const float* W; int mx;
    if (kx < 32) { W = spw1; mx = kx; } else { W = spw2; mx = kx - 32; }
    float yr[8], yi[8];
    #pragma unroll
    for (int oo = 0; oo < 8; oo++) { yr[oo] = 0.f; yi[oo] = 0.f; }
    for (int i = 0; i < CH; i++) {
        float2 z = ((const float2*)g_Z)[((size_t)(b*CH + i)*NKX + kx)*NKY + ky];
        #pragma unroll
        for (int oo = 0; oo < 8; oo++) {
            int o = og*8 + oo;
            float2 wv = ((const float2*)W)[(((size_t)i*CH + o)*MM + mx)*MM + ky];
            yr[oo] += z.x*wv.x - z.y*wv.y;
            yi[oo] += z.x*wv.y + z.y*wv.x;
        }
    }
    #pragma unroll
    for (int oo = 0; oo < 8; oo++) {
        int o = og*8 + oo;
        ((float2*)g_Yv)[((size_t)(b*CH + o)*NKX + kx)*NKY + ky] = make_float2(yr[oo], yi[oo]);
    }
}

// ============ K4: inverse H-DFT  per bo: C[528,32] = IHstack[528,128] x Ystack[128,32] ====
__global__ void k4_idfth() {
    __shared__ float AS[128*36];   // per-chunk [r][k] kc=32, stride 36
    __shared__ float BS[32*132];   // full [n=ky][k=128] stride 132
    int tid = threadIdx.x;
    int warp = tid >> 5, lane = tid & 31;
    int g = lane >> 2, t = lane & 3;
    int bo = blockIdx.x;
    int mt = blockIdx.y;           // 0..4, rows mt*128..
    float c[4][4];
    #pragma unroll
    for (int i = 0; i < 4; i++) { c[i][0]=0.f; c[i][1]=0.f; c[i][2]=0.f; c[i][3]=0.f; }

    // stage B once: Ystack[128,32]
    for (int i = tid; i < 32*128; i += 256) {
        int ky = i >> 7, k = i & 127;
        int kx = (k < 64) ? k : k - 64;
        float2 y = ((const float2*)g_Yv)[((size_t)bo*NKX + kx)*NKY + ky];
        BS[ky*132 + k] = to_tf32((k < 64) ? y.x : y.y);
    }

    for (int ch = 0; ch < 4; ch++) {
        int k0c = ch * 32;
        for (int i = tid; i < 128*32; i += 256) {
            int r = i >> 5, kk = i & 31;
            int R = mt*128 + r;
            int k = k0c + kk;
            float v = 0.f;
            if (R < 528) {
                if (R < 264) {
                    int h = R;
                    v = (k < 64) ? g_IHc[h*NKX + k] : -g_IHs[h*NKX + (k-64)];
                } else {
                    int h = R - 264;
                    v = (k < 64) ? g_IHs[h*NKX + k] :  g_IHc[h*NKX + (k-64)];
                }
            }
            AS[r*36 + kk] = to_tf32(v);
        }
        __syncthreads();
        #pragma unroll
        for (int ks = 0; ks < 4; ks++) {
            int k0 = ks * 8;
            const float* Ar = &AS[(warp*16 + g)*36 + k0 + t];
            uint32_t a0 = __float_as_uint(Ar[0]);
            uint32_t a1 = __float_as_uint(Ar[8*36]);
            uint32_t a2 = __float_as_uint(Ar[4]);
            uint32_t a3 = __float_as_uint(Ar[8*36 + 4]);
            int kg = k0c + k0;
            #pragma unroll
            for (int nt = 0; nt < 4; nt++) {
                uint32_t b0 = __float_as_uint(BS[(nt*8 + g)*132 + kg + t]);
                uint32_t b1 = __float_as_uint(BS[(nt*8 + g)*132 + kg + t + 4]);
                mma_tf32(c[nt], a0, a1, a2, a3, b0, b1);
            }
        }
        __syncthreads();
    }
    int Rb = mt*128 + warp*16 + g;
    #pragma unroll
    for (int nt = 0; nt < 4; nt++) {
        int col = nt*8 + 2*t;
        #pragma unroll
        for (int q = 0; q < 4; q++) {
            int R = Rb + (q >> 1)*8;
            if (R >= 528) continue;
            int cc = col + (q & 1);
            int h = (R < 264) ? R : R - 264;
            float* p = (float*)(((float2*)g_Z2) + ((size_t)bo*HP + h)*NKY + cc);
            p[(R < 264) ? 0 : 1] = c[nt][q];
        }
    }
}

// ============ K5a: invW GEMM  C1[135168,264] = Z2[135168,64] x Wb[64,264] ============
__global__ void k5a_invw() {
    __shared__ float BS[88*68];    // [n][k] stride 68
    int tid = threadIdx.x;
    int warp = tid >> 5, lane = tid & 31;
    int g = lane >> 2, t = lane & 3;
    size_t r0 = (size_t)blockIdx.x*128 + warp*16 + g;
    int nblk = blockIdx.y;         // 0..2, 88 cols each
    const float* Z2f = g_Z2;

    uint32_t a[8][4];
    {
        const float* A0 = Z2f + r0*64;
        const float* A1 = Z2f + (r0+8)*64;
        #pragma unroll
        for (int ks = 0; ks < 8; ks++) {
            a[ks][0] = __float_as_uint(to_tf32(A0[8*ks + t]));
            a[ks][1] = __float_as_uint(to_tf32(A1[8*ks + t]));
            a[ks][2] = __float_as_uint(to_tf32(A0[8*ks + t + 4]));
            a[ks][3] = __float_as_uint(to_tf32(A1[8*ks + t + 4]));
        }
    }
    for (int i = tid; i < 88*64; i += 256) {
        int n = i >> 6, k = i & 63;
        int w = nblk*88 + n;
        int ky = k >> 1;
        float v = (k & 1) ? -g_IWs[ky*WP + w] : g_IWc[ky*WP + w];
        BS[n*68 + k] = to_tf32(v);
    }
    __syncthreads();

    float c[11][4];
    #pragma unroll
    for (int i = 0; i < 11; i++) { c[i][0]=0.f; c[i][1]=0.f; c[i][2]=0.f; c[i][3]=0.f; }
    #pragma unroll
    for (int ks = 0; ks < 8; ks++) {
        #pragma unroll
        for (int nt = 0; nt < 11; nt++) {
            uint32_t b0 = __float_as_uint(BS[(nt*8 + g)*68 + 8*ks + t]);
            uint32_t b1 = __float_as_uint(BS[(nt*8 + g)*68 + 8*ks + t + 4]);
            mma_tf32(c[nt], a[ks][0], a[ks][1], a[ks][2], a[ks][3], b0, b1);
        }
    }
    #pragma unroll
    for (int nt = 0; nt < 11; nt++) {
        int w = nblk*88 + nt*8 + 2*t;
        *(float2*)&g_hC[r0*WP + w]     = make_float2(c[nt][0], c[nt][1]);
        *(float2*)&g_hC[(r0+8)*WP + w] = make_float2(c[nt][2], c[nt][3]);
    }
}

// ============ K5b: 1x1 conv GEMM + epilogue  per b: C[64,69696] = convW x hin[b] ==========
__global__ void k5b_conv(const float* __restrict__ hin,
                         const float* __restrict__ cw, const float* __restrict__ cb,
                         float* __restrict__ hout, int apply_gelu) {
    __shared__ float CS[64*68];    // A: conv_w [o][i] stride 68
    __shared__ float BS[64*72];    // B: hin tile [i][ww] stride 72
    int tid = threadIdx.x;
    int warp = tid >> 5, lane = tid & 31;
    int g = lane >> 2, t = lane & 3;
    int b = blockIdx.y;
    size_t hw0 = (size_t)blockIdx.x * 64;
    int mw = warp & 3, nw = warp >> 2;   // 4 M-warps x 2 N-warps

    for (int i = tid; i < 64*64; i += 256) {
        int o = i >> 6, ii = i & 63;
        CS[o*68 + ii] = to_tf32(cw[o*64 + ii]);
    }
    for (int i = tid; i < 64*64; i += 256) {
        int ii = i >> 6, ww = i & 63;
        BS[ii*72 + ww] = to_tf32(hin[((size_t)(b*CH + ii))*HW + hw0 + ww]);
    }
    __syncthreads();

    float c[4][4];
    #pragma unroll
    for (int i = 0; i < 4; i++) { c[i][0]=0.f; c[i][1]=0.f; c[i][2]=0.f; c[i][3]=0.f; }
    int o0 = mw*16, n0 = nw*32;
    #pragma unroll
    for (int ks = 0; ks < 8; ks++) {
        const float* Ar = &CS[(o0 + g)*68 + 8*ks + t];
        uint32_t a0 = __float_as_uint(Ar[0]);
        uint32_t a1 = __float_as_uint(Ar[8*68]);
        uint32_t a2 = __float_as_uint(Ar[4]);
        uint32_t a3 = __float_as_uint(Ar[8*68 + 4]);
        #pragma unroll
        for (int nt = 0; nt < 4; nt++) {
            uint32_t b0 = __float_as_uint(BS[(8*ks + t)*72 + n0 + nt*8 + g]);
            uint32_t b1 = __float_as_uint(BS[(8*ks + t + 4)*72 + n0 + nt*8 + g]);
            mma_tf32(c[nt], a0, a1, a2, a3, b0, b1);
        }
    }
    #pragma unroll
    for (int nt = 0; nt < 4; nt++) {
        int ncol = n0 + nt*8 + 2*t;
        #pragma unroll
        for (int half = 0; half < 2; half++) {
            int o = o0 + g + half*8;
            size_t idx = ((size_t)(b*CH + o))*HW + hw0 + ncol;
            float2 c1 = *(const float2*)&g_hC[idx];
            float bias = cb[o];
            float vx = c[nt][half*2 + 0] + c1.x + bias;
            float vy = c[nt][half*2 + 1] + c1.y + bias;
            if (apply_gelu) { vx = gelu_exact(vx); vy = gelu_exact(vy); }
            *(float2*)&hout[idx] = make_float2(vx, vy);
        }
    }
}

// ---------------- crop ----------------
__global__ void k_crop(const float* __restrict__ hin, float* __restrict__ out) {
    size_t idx = (size_t)blockIdx.x * blockDim.x + threadIdx.x;
    if (idx >= (size_t)BB*CH*H0*W0) return;
    int w  = (int)(idx & 255);
    int h  = (int)((idx >> 8) & 255);
    int bc = (int)(idx >> 16);
    out[idx] = hin[((size_t)bc*HP + h)*WP + w];
}

// ---------------- host launcher ----------------
extern "C" void kernel_launch(void* const* d_in, const int* in_sizes, int n_in,
                              void* d_out, int out_size) {
    const float* x       = (const float*)d_in[0];
    const float* lift_w1 = (const float*)d_in[1];
    const float* lift_b1 = (const float*)d_in[2];
    const float* lift_w2 = (const float*)d_in[3];
    const float* lift_b2 = (const float*)d_in[4];
    const float* conv_w  = (const float*)d_in[5];
    const float* conv_b  = (const float*)d_in[6];
    const float* spw1    = (const float*)d_in[7];
    const float* spw2    = (const float*)d_in[8];
    float* out = (float*)d_out;

    float *hA, *hB;
    cudaGetSymbolAddress((void**)&hA, g_hA);
    cudaGetSymbolAddress((void**)&hB, g_hB);

    k_init_basis<<<(NKX*HP + 255)/256, 256>>>();
    k_lift<<<dim3(HP, BB), 256>>>(x, lift_w1, lift_b1, lift_w2, lift_b2, hA);

    const size_t sp_stride = (size_t)CH*CH*MM*MM*2;
    for (int l = 0; l < NL; l++) {
        const float* hin  = (l & 1) ? hB : hA;
        float*       hnxt = (l & 1) ? hA : hB;
        k1_dftw<<<MROWS/128, 256>>>(hin);
        k2_dfth<<<BB*CH, 256>>>();
        k_modes<<<dim3(NKX, 8), 256>>>(spw1 + (size_t)l*sp_stride,
                                       spw2 + (size_t)l*sp_stride);
        k4_idfth<<<dim3(BB*CH, 5), 256>>>();
        k5a_invw<<<dim3(MROWS/128, 3), 256>>>();
        k5b_conv<<<dim3(HW/64, BB), 256>>>(hin,
                                           conv_w + (size_t)l*CH*CH,
                                           conv_b + (size_t)l*CH,
                                           hnxt, (l < NL-1) ? 1 : 0);
    }
    k_crop<<<(int)(((size_t)BB*CH*H0*W0 + 255)/256), 256>>>(hA, out);
}

// round 5
// speedup vs baseline: 1.6117x; 1.3216x over previous
#include <cuda_runtime.h>
#include <math.h>
#include <stdint.h>

// ---------------- problem constants ----------------
#define BB   8
#define CIN  3
#define H0   256
#define W0   256
#define CH   64
#define MIDC 32
#define NL   4
#define HP   264
#define WP   264
#define HW   (HP*WP)          // 69696
#define MROWS (BB*CH*HP)      // 135168
#define XPLANE (288*32)       // padded h-plane per bc
#define ZPLANE (64*32)
#define Z2PLANE (264*32)

// ---------------- scratch (static device globals) ----------------
__device__ __align__(16) float g_hA[(size_t)BB*CH*HW];
__device__ __align__(16) float g_hB[(size_t)BB*CH*HW];
__device__ __align__(16) float g_Xr[(size_t)512*XPLANE];
__device__ __align__(16) float g_Xi[(size_t)512*XPLANE];
__device__ __align__(16) float g_Zr[(size_t)512*ZPLANE];
__device__ __align__(16) float g_Zi[(size_t)512*ZPLANE];
__device__ __align__(16) float g_Yvr[(size_t)512*ZPLANE];
__device__ __align__(16) float g_Yvi[(size_t)512*ZPLANE];
__device__ __align__(16) float g_Z2r[(size_t)512*Z2PLANE];
__device__ __align__(16) float g_Z2i[(size_t)512*Z2PLANE];
// precomputed tf32 basis matrices
__device__ __align__(16) float g_E2 [128*576];   // K2 A: [r][k] (stacked fwd-H, padded K)
__device__ __align__(16) float g_I2 [640*128];   // K4 A: [R][k] (stacked inv-H, padded M)
__device__ __align__(16) float g_K1B[64*288];    // K1 B: [n][k] (fwd-W, padded K)
__device__ __align__(16) float g_K5B[64*264];    // K5 spectral B: [k][w] (inv-W stacked)

__device__ __forceinline__ float gelu_exact(float v) {
    return 0.5f * v * (1.0f + erff(v * 0.70710678118654752f));
}
__device__ __forceinline__ float to_tf32(float x) {
    uint32_t u; asm("cvt.rna.tf32.f32 %0, %1;" : "=r"(u) : "f"(x));
    return __uint_as_float(u);
}
__device__ __forceinline__ float4 tf4(float4 v) {
    v.x = to_tf32(v.x); v.y = to_tf32(v.y); v.z = to_tf32(v.z); v.w = to_tf32(v.w);
    return v;
}
__device__ __forceinline__ void mma_tf32(float c[4], uint32_t a0, uint32_t a1,
                                         uint32_t a2, uint32_t a3,
                                         uint32_t b0, uint32_t b1) {
    asm volatile("mma.sync.aligned.m16n8k8.row.col.f32.tf32.tf32.f32 "
                 "{%0,%1,%2,%3},{%4,%5,%6,%7},{%8,%9},{%0,%1,%2,%3};"
                 : "+f"(c[0]), "+f"(c[1]), "+f"(c[2]), "+f"(c[3])
                 : "r"(a0), "r"(a1), "r"(a2), "r"(a3), "r"(b0), "r"(b1));
}

// ---------------- init: build all basis matrices + zero pads ----------------
#define E2_END   73728
#define I2_END   155648
#define K1B_END  174080
#define K5B_END  190976
#define PAD_END  (190976 + 786432)

__global__ void k_init() {
    long long idx = (long long)blockIdx.x * blockDim.x + threadIdx.x;
    const double PI2 = 6.283185307179586476925286766559;
    if (idx < E2_END) {                       // g_E2 [128][576]
        int r = (int)(idx / 576), k = (int)(idx % 576);
        int kx = r & 63; int kxv = (kx < 32) ? kx : kx + 200;
        int kp = (k < 288) ? k : k - 288;
        float v = 0.f;
        if (kp < 264) {
            double th = PI2 * (double)((kxv * kp) % 264) / 264.0;
            double c = cos(th), s = sin(th);
            if (k < 288) v = (float)((r < 64) ? c : -s);
            else         v = (float)((r < 64) ? s :  c);
        }
        g_E2[idx] = to_tf32(v);
    } else if (idx < I2_END) {                // g_I2 [640][128]
        int j = (int)(idx - E2_END);
        int R = j / 128, k = j % 128;
        float v = 0.f;
        if (R < 528) {
            int h = (R < 264) ? R : R - 264;
            int kx = k & 63; int kxv = (kx < 32) ? kx : kx + 200;
            double th = PI2 * (double)((kxv * h) % 264) / 264.0;
            double c = cos(th) / 264.0, s = sin(th) / 264.0;
            if (R < 264) v = (float)((k < 64) ? c : -s);
            else         v = (float)((k < 64) ? s :  c);
        }
        g_I2[j] = to_tf32(v);
    } else if (idx < K1B_END) {               // g_K1B [64][288]
        int j = (int)(idx - I2_END);
        int n = j / 288, k = j % 288;
        float v = 0.f;
        if (k < 264) {
            int ky = n >> 1;
            double th = PI2 * (double)((ky * k) % 264) / 264.0;
            v = (float)((n & 1) ? -sin(th) : cos(th));
        }
        g_K1B[j] = to_tf32(v);
    } else if (idx < K5B_END) {               // g_K5B [64][264]
        int j = (int)(idx - K1B_END);
        int k = j / 264, w = j % 264;
        int ky = k & 31;
        double wgt = ((ky == 0) ? 1.0 : 2.0) / 264.0;
        double th = PI2 * (double)((ky * w) % 264) / 264.0;
        double v = (k < 32) ? wgt * cos(th) : -wgt * sin(th);
        g_K5B[j] = to_tf32((float)v);
    } else if (idx < PAD_END) {               // zero X pads h in [264,288)
        long long j = idx - K5B_END;
        int ky = (int)(j & 31);
        int hh = (int)((j >> 5) % 24);
        long long rest = (j >> 5) / 24;
        int bc = (int)(rest & 511);
        int pl = (int)(rest >> 9);
        float* dst = pl ? g_Xi : g_Xr;
        dst[(size_t)bc * XPLANE + (264 + hh) * 32 + ky] = 0.f;
    }
}

// ---------------- lift ----------------
__global__ void k_lift(const float* __restrict__ x,
                       const float* __restrict__ w1, const float* __restrict__ b1,
                       const float* __restrict__ w2, const float* __restrict__ b2,
                       float* __restrict__ hout) {
    int h = blockIdx.x, b = blockIdx.y;
    for (int w = threadIdx.x; w < WP; w += blockDim.x) {
        size_t base = ((size_t)b*CH)*HW + (size_t)h*WP + (size_t)w;
        if (h >= H0 || w >= W0) {
            for (int o = 0; o < CH; o++) hout[base + (size_t)o*HW] = 0.0f;
            continue;
        }
        float in5[5];
        #pragma unroll
        for (int c = 0; c < CIN; c++)
            in5[c] = x[(((size_t)b*CIN + c)*H0 + h)*W0 + w];
        in5[3] = (float)h * (1.0f/255.0f);
        in5[4] = (float)w * (1.0f/255.0f);
        float mid[MIDC];
        #pragma unroll
        for (int m = 0; m < MIDC; m++) {
            float s = b1[m];
            #pragma unroll
            for (int i = 0; i < 5; i++) s += w1[m*5 + i] * in5[i];
            mid[m] = gelu_exact(s);
        }
        #pragma unroll 8
        for (int o = 0; o < CH; o++) {
            float s = b2[o];
            #pragma unroll
            for (int m = 0; m < MIDC; m++) s += w2[o*MIDC + m] * mid[m];
            hout[base + (size_t)o*HW] = s;
        }
    }
}

// ============ K1: W-rDFT GEMM  C[135168,64] = hin[135168,264pad288] x K1B^T ============
// dyn smem: BS[64][292] + AS[128][36]
__global__ void k1_dftw(const float* __restrict__ hin) {
    extern __shared__ float sm[];
    float* BS = sm;                 // [n=64][k=292]
    float* AS = sm + 64*292;        // [r=128][k=36]
    int tid = threadIdx.x;
    int warp = tid >> 5, lane = tid & 31;
    int g = lane >> 2, t = lane & 3;
    size_t row0 = (size_t)blockIdx.x * 128;

    // stage full B (pre-tf32)
    {
        int n = tid >> 2, tc = tid & 3;
        for (int q = tc; q < 72; q += 4)
            *(float4*)&BS[n*292 + q*4] = *(const float4*)&g_K1B[n*288 + q*4];
    }

    float c[8][4];
    #pragma unroll
    for (int i = 0; i < 8; i++) { c[i][0]=0.f; c[i][1]=0.f; c[i][2]=0.f; c[i][3]=0.f; }

    for (int ch = 0; ch < 9; ch++) {
        int k0 = ch * 32;
        if (k0 + 32 <= 264) {
            for (int i = tid; i < 1024; i += 256) {
                int r = i >> 3, q = i & 7;
                float4 v = tf4(*(const float4*)&hin[(row0 + r)*264 + k0 + q*4]);
                *(float4*)&AS[r*36 + q*4] = v;
            }
        } else {
            for (int i = tid; i < 4096; i += 256) {
                int r = i >> 5, kk = i & 31;
                int k = k0 + kk;
                AS[r*36 + kk] = (k < 264) ? to_tf32(hin[(row0 + r)*264 + k]) : 0.f;
            }
        }
        __syncthreads();
        #pragma unroll
        for (int ks = 0; ks < 4; ks++) {
            int kl = ks * 8;
            const float* Ar = &AS[(warp*16 + g)*36 + kl + t];
            uint32_t a0 = __float_as_uint(Ar[0]);
            uint32_t a1 = __float_as_uint(Ar[8*36]);
            uint32_t a2 = __float_as_uint(Ar[4]);
            uint32_t a3 = __float_as_uint(Ar[8*36 + 4]);
            int kg = k0 + kl;
            #pragma unroll
            for (int nt = 0; nt < 8; nt++) {
                uint32_t b0 = __float_as_uint(BS[(nt*8 + g)*292 + kg + t]);
                uint32_t b1 = __float_as_uint(BS[(nt*8 + g)*292 + kg + t + 4]);
                mma_tf32(c[nt], a0, a1, a2, a3, b0, b1);
            }
        }
        __syncthreads();
    }
    int r1 = (int)row0 + warp*16 + g;
    int r2 = r1 + 8;
    int bc1 = r1 / 264, h1 = r1 % 264;
    int bc2 = r2 / 264, h2 = r2 % 264;
    size_t o1 = (size_t)bc1*XPLANE + h1*32;
    size_t o2 = (size_t)bc2*XPLANE + h2*32;
    #pragma unroll
    for (int nt = 0; nt < 8; nt++) {
        int ky = nt*4 + t;
        g_Xr[o1 + ky] = c[nt][0]; g_Xi[o1 + ky] = c[nt][1];
        g_Xr[o2 + ky] = c[nt][2]; g_Xi[o2 + ky] = c[nt][3];
    }
}

// ============ K2: fwd H-DFT, batch 2 bc:  C[128, 64] = E2[128,576] x Xstack ============
__global__ void k2_dfth() {
    __shared__ float AS[128*36];
    __shared__ float BS[32*68];
    int tid = threadIdx.x;
    int warp = tid >> 5, lane = tid & 31;
    int g = lane >> 2, t = lane & 3;
    int bc0 = blockIdx.x * 2;

    float c[8][4];
    #pragma unroll
    for (int i = 0; i < 8; i++) { c[i][0]=0.f; c[i][1]=0.f; c[i][2]=0.f; c[i][3]=0.f; }

    for (int ch = 0; ch < 18; ch++) {
        const float* plane = (ch < 9) ? g_Xr : g_Xi;
        int h0 = ((ch < 9) ? ch : ch - 9) * 32;
        // stage B [32k][64n]
        for (int i = tid; i < 512; i += 256) {
            int k = i >> 4, n4 = i & 15;
            int bcl = n4 >> 3, kyq = (n4 & 7) * 4;
            float4 v = tf4(*(const float4*)&plane[(size_t)(bc0 + bcl)*XPLANE + (h0 + k)*32 + kyq]);
            *(float4*)&BS[k*68 + bcl*32 + kyq] = v;
        }
        // stage A [128][32] from g_E2 (pre-tf32)
        for (int i = tid; i < 1024; i += 256) {
            int r = i >> 3, q = i & 7;
            *(float4*)&AS[r*36 + q*4] = *(const float4*)&g_E2[r*576 + ch*32 + q*4];
        }
        __syncthreads();
        #pragma unroll
        for (int ks = 0; ks < 4; ks++) {
            int kl = ks * 8;
            const float* Ar = &AS[(warp*16 + g)*36 + kl + t];
            uint32_t a0 = __float_as_uint(Ar[0]);
            uint32_t a1 = __float_as_uint(Ar[8*36]);
            uint32_t a2 = __float_as_uint(Ar[4]);
            uint32_t a3 = __float_as_uint(Ar[8*36 + 4]);
            #pragma unroll
            for (int nt = 0; nt < 8; nt++) {
                uint32_t b0 = __float_as_uint(BS[(kl + t)*68 + nt*8 + g]);
                uint32_t b1 = __float_as_uint(BS[(kl + t + 4)*68 + nt*8 + g]);
                mma_tf32(c[nt], a0, a1, a2, a3, b0, b1);
            }
        }
        __syncthreads();
    }
    // epilogue: rows of this warp all in one half (m0 multiple of 16)
    int m0 = warp * 16;
    float* P = (m0 < 64) ? g_Zr : g_Zi;
    int kx1 = (m0 & 63) + g, kx2 = kx1 + 8;
    #pragma unroll
    for (int nt = 0; nt < 8; nt++) {
        int col = nt*8 + 2*t;
        int bcl = col >> 5, kyc = col & 31;
        size_t b1 = (size_t)(bc0 + bcl)*ZPLANE + kx1*32 + kyc;
        size_t b2 = (size_t)(bc0 + bcl)*ZPLANE + kx2*32 + kyc;
        *(float2*)&P[b1] = make_float2(c[nt][0], c[nt][1]);
        *(float2*)&P[b2] = make_float2(c[nt][2], c[nt][3]);
    }
}

// ============ K3: per-mode complex 64x64 channel mixing (fp32, planar I/O) ============
__global__ void k_modes(const float* __restrict__ spw1, const float* __restrict__ spw2) {
    int kx = blockIdx.x;
    int og = blockIdx.y;
    int ky = threadIdx.x & 31;
    int b  = threadIdx.x >> 5;
    const float* W; int mx;
    if (kx < 32) { W = spw1; mx = kx; } else { W = spw2; mx = kx - 32; }
    float yr[8], yi[8];
    #pragma unroll
    for (int oo = 0; oo < 8; oo++) { yr[oo] = 0.f; yi[oo] = 0.f; }
    for (int i = 0; i < CH; i++) {
        size_t zi_idx = (size_t)(b*CH + i)*ZPLANE + kx*32 + ky;
        float zr = g_Zr[zi_idx], zim = g_Zi[zi_idx];
        #pragma unroll
        for (int oo = 0; oo < 8; oo++) {
            int o = og*8 + oo;
            const float* wp = W + (((size_t)i*CH + o)*32 + mx)*32*2 + ky*2;
            float wr = wp[0], wi = wp[1];
            yr[oo] += zr*wr - zim*wi;
            yi[oo] += zr*wi + zim*wr;
        }
    }
    #pragma unroll
    for (int oo = 0; oo < 8; oo++) {
        int o = og*8 + oo;
        size_t idx = (size_t)(b*CH + o)*ZPLANE + kx*32 + ky;
        g_Yvr[idx] = yr[oo];
        g_Yvi[idx] = yi[oo];
    }
}

// ============ K4: inv H-DFT, batch 4 bo:  C[640pad,128] = I2[640,128] x Ystack ============
// dyn smem: BS[128][132] + AS[128][36]
__global__ void k4_idfth() {
    extern __shared__ float sm[];
    float* BS = sm;                 // [k=128][n=132]
    float* AS = sm + 128*132;       // [r=128][k=36]
    int tid = threadIdx.x;
    int warp = tid >> 5, lane = tid & 31;
    int g = lane >> 2, t = lane & 3;
    int bog = blockIdx.x;
    int mt  = blockIdx.y;

    // stage full B [128][128]
    for (int i = tid; i < 4096; i += 256) {
        int k = i >> 5, n4 = i & 31;
        int bol = n4 >> 3, kyq = (n4 & 7) * 4;
        const float* src = (k < 64)
            ? &g_Yvr[(size_t)(bog*4 + bol)*ZPLANE + k*32 + kyq]
            : &g_Yvi[(size_t)(bog*4 + bol)*ZPLANE + (k-64)*32 + kyq];
        *(float4*)&BS[k*132 + bol*32 + kyq] = tf4(*(const float4*)src);
    }

    float c[16][4];
    #pragma unroll
    for (int i = 0; i < 16; i++) { c[i][0]=0.f; c[i][1]=0.f; c[i][2]=0.f; c[i][3]=0.f; }

    for (int ch = 0; ch < 4; ch++) {
        for (int i = tid; i < 1024; i += 256) {
            int r = i >> 3, q = i & 7;
            *(float4*)&AS[r*36 + q*4] = *(const float4*)&g_I2[(size_t)(mt*128 + r)*128 + ch*32 + q*4];
        }
        __syncthreads();
        #pragma unroll
        for (int ks = 0; ks < 4; ks++) {
            int kl = ks * 8;
            const float* Ar = &AS[(warp*16 + g)*36 + kl + t];
            uint32_t a0 = __float_as_uint(Ar[0]);
            uint32_t a1 = __float_as_uint(Ar[8*36]);
            uint32_t a2 = __float_as_uint(Ar[4]);
            uint32_t a3 = __float_as_uint(Ar[8*36 + 4]);
            int kg = ch*32 + kl;
            #pragma unroll
            for (int nt = 0; nt < 16; nt++) {
                uint32_t b0 = __float_as_uint(BS[(kg + t)*132 + nt*8 + g]);
                uint32_t b1 = __float_as_uint(BS[(kg + t + 4)*132 + nt*8 + g]);
                mma_tf32(c[nt], a0, a1, a2, a3, b0, b1);
            }
        }
        __syncthreads();
    }
    int R1 = mt*128 + warp*16 + g;
    int R2 = R1 + 8;
    #pragma unroll
    for (int nt = 0; nt < 16; nt++) {
        int col = nt*8 + 2*t;
        int bol = col >> 5, kyc = col & 31;
        if (R1 < 528) {
            int h = (R1 < 264) ? R1 : R1 - 264;
            float* P = (R1 < 264) ? g_Z2r : g_Z2i;
            *(float2*)&P[(size_t)(bog*4 + bol)*Z2PLANE + h*32 + kyc] = make_float2(c[nt][0], c[nt][1]);
        }
        if (R2 < 528) {
            int h = (R2 < 264) ? R2 : R2 - 264;
            float* P = (R2 < 264) ? g_Z2r : g_Z2i;
            *(float2*)&P[(size_t)(bog*4 + bol)*Z2PLANE + h*32 + kyc] = make_float2(c[nt][2], c[nt][3]);
        }
    }
}

// ============ K5 fused: conv GEMM + spectral invW GEMM + bias + gelu ============
// grid (3 wtiles of 88, HP, BB); 8 warps: 0-3 conv, 4-7 spectral
// dyn smem: CW[64][68] + ZS[64][68] + HB[64][92] + WB[64][92] (WB reused as spill)
__global__ void k5_fused(const float* __restrict__ hin,
                         const float* __restrict__ cw, const float* __restrict__ cb,
                         float* __restrict__ hout, int apply_gelu) {
    extern __shared__ float sm[];
    float* CW = sm;                 // 64*68
    float* ZS = sm + 4352;          // 64*68
    float* HB = sm + 8704;          // 64*92
    float* WB = sm + 14592;         // 64*92 (spectral B, then spill)
    int tid = threadIdx.x;
    int warp = tid >> 5, lane = tid & 31;
    int g = lane >> 2, t = lane & 3;
    int wt = blockIdx.x, h = blockIdx.y, b = blockIdx.z;
    int w0 = wt * 88;

    // stage A matrices
    for (int i = tid; i < 1024; i += 256) {
        int o = i >> 4, q = i & 15;
        *(float4*)&CW[o*68 + q*4] = tf4(*(const float4*)&cw[o*64 + q*4]);
        int k4 = q * 4;
        const float* src = (k4 < 32)
            ? &g_Z2r[(size_t)(b*CH + o)*Z2PLANE + h*32 + k4]
            : &g_Z2i[(size_t)(b*CH + o)*Z2PLANE + h*32 + (k4 - 32)];
        *(float4*)&ZS[o*68 + k4] = tf4(*(const float4*)src);
    }
    // stage B matrices: rows = 64, 22 float4 per row
    {
        int row = tid >> 2, tc = tid & 3;
        for (int q = tc; q < 22; q += 4) {
            *(float4*)&HB[row*92 + q*4] =
                tf4(*(const float4*)&hin[(size_t)(b*CH + row)*HW + (size_t)h*264 + w0 + q*4]);
            *(float4*)&WB[row*92 + q*4] = *(const float4*)&g_K5B[row*264 + w0 + q*4];
        }
    }
    __syncthreads();

    int grp = warp >> 2;            // 0 = conv, 1 = spectral
    int m0 = (warp & 3) * 16;
    const float* Ab = grp ? ZS : CW;
    const float* Bb = grp ? WB : HB;

    float c[11][4];
    #pragma unroll
    for (int i = 0; i < 11; i++) { c[i][0]=0.f; c[i][1]=0.f; c[i][2]=0.f; c[i][3]=0.f; }

    #pragma unroll
    for (int ks = 0; ks < 8; ks++) {
        const float* Ar = &Ab[(m0 + g)*68 + ks*8 + t];
        uint32_t a0 = __float_as_uint(Ar[0]);
        uint32_t a1 = __float_as_uint(Ar[8*68]);
        uint32_t a2 = __float_as_uint(Ar[4]);
        uint32_t a3 = __float_as_uint(Ar[8*68 + 4]);
        #pragma unroll
        for (int nt = 0; nt < 11; nt++) {
            uint32_t b0 = __float_as_uint(Bb[(ks*8 + t)*92 + nt*8 + g]);
            uint32_t b1 = __float_as_uint(Bb[(ks*8 + t + 4)*92 + nt*8 + g]);
            mma_tf32(c[nt], a0, a1, a2, a3, b0, b1);
        }
    }
    __syncthreads();   // all GEMMs done; WB free for reuse

    if (grp == 1) {    // spectral warps spill C into WB
        #pragma unroll
        for (int nt = 0; nt < 11; nt++) {
            int col = nt*8 + 2*t;
            *(float2*)&WB[(m0 + g)*92 + col]     = make_float2(c[nt][0], c[nt][1]);
            *(float2*)&WB[(m0 + g + 8)*92 + col] = make_float2(c[nt][2], c[nt][3]);
        }
    }
    __syncthreads();

    if (grp == 0) {    // conv warps: combine + epilogue
        #pragma unroll
        for (int nt = 0; nt < 11; nt++) {
            int col = nt*8 + 2*t;
            #pragma unroll
            for (int half = 0; half < 2; half++) {
                int o = m0 + g + half*8;
                float2 sp = *(const float2*)&WB[o*92 + col];
                float bias = cb[o];
                float vx = c[nt][half*2 + 0] + sp.x + bias;
                float vy = c[nt][half*2 + 1] + sp.y + bias;
                if (apply_gelu) { vx = gelu_exact(vx); vy = gelu_exact(vy); }
                *(float2*)&hout[(size_t)(b*CH + o)*HW + (size_t)h*264 + w0 + col] =
                    make_float2(vx, vy);
            }
        }
    }
}

// ---------------- crop ----------------
__global__ void k_crop(const float* __restrict__ hin, float* __restrict__ out) {
    size_t idx = (size_t)blockIdx.x * blockDim.x + threadIdx.x;
    if (idx >= (size_t)BB*CH*H0*W0) return;
    int w  = (int)(idx & 255);
    int h  = (int)((idx >> 8) & 255);
    int bc = (int)(idx >> 16);
    out[idx] = hin[((size_t)bc*HP + h)*WP + w];
}

// ---------------- host launcher ----------------
extern "C" void kernel_launch(void* const* d_in, const int* in_sizes, int n_in,
                              void* d_out, int out_size) {
    const float* x       = (const float*)d_in[0];
    const float* lift_w1 = (const float*)d_in[1];
    const float* lift_b1 = (const float*)d_in[2];
    const float* lift_w2 = (const float*)d_in[3];
    const float* lift_b2 = (const float*)d_in[4];
    const float* conv_w  = (const float*)d_in[5];
    const float* conv_b  = (const float*)d_in[6];
    const float* spw1    = (const float*)d_in[7];
    const float* spw2    = (const float*)d_in[8];
    float* out = (float*)d_out;

    float *hA, *hB;
    cudaGetSymbolAddress((void**)&hA, g_hA);
    cudaGetSymbolAddress((void**)&hB, g_hB);

    const int K1_SMEM = (64*292 + 128*36) * 4;     // 93184
    const int K4_SMEM = (128*132 + 128*36) * 4;    // 86016
    const int K5_SMEM = (4352 + 4352 + 5888 + 5888) * 4; // 81920
    cudaFuncSetAttribute(k1_dftw,  cudaFuncAttributeMaxDynamicSharedMemorySize, K1_SMEM);
    cudaFuncSetAttribute(k4_idfth, cudaFuncAttributeMaxDynamicSharedMemorySize, K4_SMEM);
    cudaFuncSetAttribute(k5_fused, cudaFuncAttributeMaxDynamicSharedMemorySize, K5_SMEM);

    k_init<<<(PAD_END + 255)/256, 256>>>();
    k_lift<<<dim3(HP, BB), 256>>>(x, lift_w1, lift_b1, lift_w2, lift_b2, hA);

    const size_t sp_stride = (size_t)CH*CH*32*32*2;
    for (int l = 0; l < NL; l++) {
        const float* hin  = (l & 1) ? hB : hA;
        float*       hnxt = (l & 1) ? hA : hB;
        k1_dftw<<<MROWS/128, 256, K1_SMEM>>>(hin);
        k2_dfth<<<256, 256>>>();
        k_modes<<<dim3(64, 8), 256>>>(spw1 + (size_t)l*sp_stride,
                                      spw2 + (size_t)l*sp_stride);
        k4_idfth<<<dim3(128, 5), 256, K4_SMEM>>>();
        k5_fused<<<dim3(3, HP, BB), 256, K5_SMEM>>>(hin,
                                                    conv_w + (size_t)l*CH*CH,
                                                    conv_b + (size_t)l*CH,
                                                    hnxt, (l < NL-1) ? 1 : 0);
    }
    k_crop<<<(int)(((size_t)BB*CH*H0*W0 + 255)/256), 256>>>(hA, out);
}

// round 7
// speedup vs baseline: 2.2052x; 1.3683x over previous
#include <cuda_runtime.h>
#include <math.h>
#include <stdint.h>

// ---------------- problem constants ----------------
#define BB   8
#define CIN  3
#define H0   256
#define W0   256
#define CH   64
#define MIDC 32
#define NL   4
#define HP   264
#define WP   264
#define HW   (HP*WP)          // 69696
#define MROWS (BB*CH*HP)      // 135168
#define XPLANE (288*32)
#define ZPLANE (64*32)
#define Z2PLANE (264*32)

// ---------------- scratch ----------------
__device__ __align__(16) float g_hA[(size_t)BB*CH*HW];
__device__ __align__(16) float g_hB[(size_t)BB*CH*HW];
__device__ __align__(16) float g_Xr[(size_t)512*XPLANE];
__device__ __align__(16) float g_Xi[(size_t)512*XPLANE];
__device__ __align__(16) float g_Zr[(size_t)512*ZPLANE];
__device__ __align__(16) float g_Zi[(size_t)512*ZPLANE];
__device__ __align__(16) float g_Yvr[(size_t)512*ZPLANE];
__device__ __align__(16) float g_Yvi[(size_t)512*ZPLANE];
__device__ __align__(16) float g_Z2r[(size_t)512*Z2PLANE];
__device__ __align__(16) float g_Z2i[(size_t)512*Z2PLANE];
__device__ __align__(16) float g_E2 [128*576];
__device__ __align__(16) float g_I2 [640*128];
__device__ __align__(16) float g_K1B[64*288];
__device__ __align__(16) float g_K5B[64*264];

__device__ __forceinline__ float gelu_exact(float v) {
    return 0.5f * v * (1.0f + erff(v * 0.70710678118654752f));
}
__device__ __forceinline__ float to_tf32(float x) {
    uint32_t u; asm("cvt.rna.tf32.f32 %0, %1;" : "=r"(u) : "f"(x));
    return __uint_as_float(u);
}
__device__ __forceinline__ float4 tf4(float4 v) {
    v.x = to_tf32(v.x); v.y = to_tf32(v.y); v.z = to_tf32(v.z); v.w = to_tf32(v.w);
    return v;
}
__device__ __forceinline__ void mma_tf32(float c[4], uint32_t a0, uint32_t a1,
                                         uint32_t a2, uint32_t a3,
                                         uint32_t b0, uint32_t b1) {
    asm volatile("mma.sync.aligned.m16n8k8.row.col.f32.tf32.tf32.f32 "
                 "{%0,%1,%2,%3},{%4,%5,%6,%7},{%8,%9},{%0,%1,%2,%3};"
                 : "+f"(c[0]), "+f"(c[1]), "+f"(c[2]), "+f"(c[3])
                 : "r"(a0), "r"(a1), "r"(a2), "r"(a3), "r"(b0), "r"(b1));
}
__device__ __forceinline__ uint32_t smem_u32(const void* p) {
    return (uint32_t)__cvta_generic_to_shared(p);
}
__device__ __forceinline__ void cp16(uint32_t dst, const void* src) {
    asm volatile("cp.async.cg.shared.global [%0], [%1], 16;" :: "r"(dst), "l"(src));
}
__device__ __forceinline__ void cp16z(uint32_t dst, const void* src, int bytes) {
    asm volatile("cp.async.cg.shared.global [%0], [%1], 16, %2;"
                 :: "r"(dst), "l"(src), "r"(bytes));
}
#define CP_COMMIT()   asm volatile("cp.async.commit_group;" ::: "memory")
#define CP_WAIT_ALL() asm volatile("cp.async.wait_group 0;" ::: "memory")

// ---------------- init: basis matrices + X pads ----------------
#define E2_END   73728
#define I2_END   155648
#define K1B_END  174080
#define K5B_END  190976
#define PAD_END  (190976 + 786432)

__global__ void k_init() {
    long long idx = (long long)blockIdx.x * blockDim.x + threadIdx.x;
    const double PI2 = 6.283185307179586476925286766559;
    if (idx < E2_END) {
        int r = (int)(idx / 576), k = (int)(idx % 576);
        int kx = r & 63; int kxv = (kx < 32) ? kx : kx + 200;
        int kp = (k < 288) ? k : k - 288;
        float v = 0.f;
        if (kp < 264) {
            double th = PI2 * (double)((kxv * kp) % 264) / 264.0;
            double c = cos(th), s = sin(th);
            if (k < 288) v = (float)((r < 64) ? c : -s);
            else         v = (float)((r < 64) ? s :  c);
        }
        g_E2[idx] = to_tf32(v);
    } else if (idx < I2_END) {
        int j = (int)(idx - E2_END);
        int R = j / 128, k = j % 128;
        float v = 0.f;
        if (R < 528) {
            int h = (R < 264) ? R : R - 264;
            int kx = k & 63; int kxv = (kx < 32) ? kx : kx + 200;
            double th = PI2 * (double)((kxv * h) % 264) / 264.0;
            double c = cos(th) / 264.0, s = sin(th) / 264.0;
            if (R < 264) v = (float)((k < 64) ? c : -s);
            else         v = (float)((k < 64) ? s :  c);
        }
        g_I2[j] = to_tf32(v);
    } else if (idx < K1B_END) {
        int j = (int)(idx - I2_END);
        int n = j / 288, k = j % 288;
        float v = 0.f;
        if (k < 264) {
            int ky = n >> 1;
            double th = PI2 * (double)((ky * k) % 264) / 264.0;
            v = (float)((n & 1) ? -sin(th) : cos(th));
        }
        g_K1B[j] = to_tf32(v);
    } else if (idx < K5B_END) {
        int j = (int)(idx - K1B_END);
        int k = j / 264, w = j % 264;
        int ky = k & 31;
        double wgt = ((ky == 0) ? 1.0 : 2.0) / 264.0;
        double th = PI2 * (double)((ky * w) % 264) / 264.0;
        double v = (k < 32) ? wgt * cos(th) : -wgt * sin(th);
        g_K5B[j] = to_tf32((float)v);
    } else if (idx < PAD_END) {
        long long j = idx - K5B_END;
        int ky = (int)(j & 31);
        int hh = (int)((j >> 5) % 24);
        long long rest = (j >> 5) / 24;
        int bc = (int)(rest & 511);
        int pl = (int)(rest >> 9);
        float* dst = pl ? g_Xi : g_Xr;
        dst[(size_t)bc * XPLANE + (264 + hh) * 32 + ky] = 0.f;
    }
}

// ---------------- lift (stores tf32-rounded activations) ----------------
__global__ void k_lift(const float* __restrict__ x,
                       const float* __restrict__ w1, const float* __restrict__ b1,
                       const float* __restrict__ w2, const float* __restrict__ b2,
                       float* __restrict__ hout) {
    int h = blockIdx.x, b = blockIdx.y;
    for (int w = threadIdx.x; w < WP; w += blockDim.x) {
        size_t base = ((size_t)b*CH)*HW + (size_t)h*WP + (size_t)w;
        if (h >= H0 || w >= W0) {
            for (int o = 0; o < CH; o++) hout[base + (size_t)o*HW] = 0.0f;
            continue;
        }
        float in5[5];
        #pragma unroll
        for (int c = 0; c < CIN; c++)
            in5[c] = x[(((size_t)b*CIN + c)*H0 + h)*W0 + w];
        in5[3] = (float)h * (1.0f/255.0f);
        in5[4] = (float)w * (1.0f/255.0f);
        float mid[MIDC];
        #pragma unroll
        for (int m = 0; m < MIDC; m++) {
            float s = b1[m];
            #pragma unroll
            for (int i = 0; i < 5; i++) s += w1[m*5 + i] * in5[i];
            mid[m] = gelu_exact(s);
        }
        #pragma unroll 8
        for (int o = 0; o < CH; o++) {
            float s = b2[o];
            #pragma unroll
            for (int m = 0; m < MIDC; m++) s += w2[o*MIDC + m] * mid[m];
            hout[base + (size_t)o*HW] = to_tf32(s);
        }
    }
}

// ============ K1: W-rDFT GEMM, cp.async double-buffered ============
// dyn smem: AS 2x[128][36] + BS 2x[64][36]  = 55296 B
__global__ void k1_dftw(const float* __restrict__ hin) {
    extern __shared__ float sm[];
    float* AS = sm;                 // 2 bufs of 128*36
    float* BS = sm + 2*128*36;      // 2 bufs of 64*36
    int tid = threadIdx.x;
    int warp = tid >> 5, lane = tid & 31;
    int g = lane >> 2, t = lane & 3;
    size_t row0 = (size_t)blockIdx.x * 128;

    auto stage = [&](int ch, int buf) {
        int k0 = ch * 32;
        float* Ad = AS + buf*128*36;
        for (int i = tid; i < 1024; i += 256) {       // A: 128 rows x 8 f4
            int r = i >> 3, q = i & 7;
            int k = k0 + q*4;
            const float* src = &hin[(row0 + r)*264 + ((k < 264) ? k : 0)];
            cp16z(smem_u32(&Ad[r*36 + q*4]), src, (k < 264) ? 16 : 0);
        }
        float* Bd = BS + buf*64*36;
        for (int i = tid; i < 512; i += 256) {        // B: 64 rows x 8 f4
            int n = i >> 3, q = i & 7;
            cp16(smem_u32(&Bd[n*36 + q*4]), &g_K1B[n*288 + k0 + q*4]);
        }
    };

    float c[8][4];
    #pragma unroll
    for (int i = 0; i < 8; i++) { c[i][0]=0.f; c[i][1]=0.f; c[i][2]=0.f; c[i][3]=0.f; }

    stage(0, 0); CP_COMMIT();
    for (int ch = 0; ch < 9; ch++) {
        CP_WAIT_ALL();
        __syncthreads();
        if (ch + 1 < 9) { stage(ch + 1, (ch + 1) & 1); CP_COMMIT(); }
        const float* Ab = AS + (ch & 1)*128*36;
        const float* Bb = BS + (ch & 1)*64*36;
        #pragma unroll
        for (int ks = 0; ks < 4; ks++) {
            int kl = ks * 8;
            const float* Ar = &Ab[(warp*16 + g)*36 + kl + t];
            uint32_t a0 = __float_as_uint(Ar[0]);
            uint32_t a1 = __float_as_uint(Ar[8*36]);
            uint32_t a2 = __float_as_uint(Ar[4]);
            uint32_t a3 = __float_as_uint(Ar[8*36 + 4]);
            #pragma unroll
            for (int nt = 0; nt < 8; nt++) {
                uint32_t b0 = __float_as_uint(Bb[(nt*8 + g)*36 + kl + t]);
                uint32_t b1 = __float_as_uint(Bb[(nt*8 + g)*36 + kl + t + 4]);
                mma_tf32(c[nt], a0, a1, a2, a3, b0, b1);
            }
        }
        __syncthreads();
    }
    int r1 = (int)row0 + warp*16 + g;
    int r2 = r1 + 8;
    int bc1 = r1 / 264, h1 = r1 % 264;
    int bc2 = r2 / 264, h2 = r2 % 264;
    size_t o1 = (size_t)bc1*XPLANE + h1*32;
    size_t o2 = (size_t)bc2*XPLANE + h2*32;
    #pragma unroll
    for (int nt = 0; nt < 8; nt++) {
        int ky = nt*4 + t;
        g_Xr[o1 + ky] = to_tf32(c[nt][0]); g_Xi[o1 + ky] = to_tf32(c[nt][1]);
        g_Xr[o2 + ky] = to_tf32(c[nt][2]); g_Xi[o2 + ky] = to_tf32(c[nt][3]);
    }
}

// ============ K2: fwd H-DFT, batch 4 bc (N=128), cp.async double-buffered ============
// dyn smem: AS 2x[128][36] + BS 2x[32][132] = 70656 B
__global__ void k2_dfth() {
    extern __shared__ float sm[];
    float* AS = sm;                 // 2 bufs 128*36
    float* BS = sm + 2*128*36;      // 2 bufs 32*132
    int tid = threadIdx.x;
    int warp = tid >> 5, lane = tid & 31;
    int g = lane >> 2, t = lane & 3;
    int bc0 = blockIdx.x * 4;

    auto stage = [&](int ch, int buf) {
        const float* plane = (ch < 9) ? g_Xr : g_Xi;
        int h0 = ((ch < 9) ? ch : ch - 9) * 32;
        float* Ad = AS + buf*128*36;
        for (int i = tid; i < 1024; i += 256) {       // A: 128 x 8 f4
            int r = i >> 3, q = i & 7;
            cp16(smem_u32(&Ad[r*36 + q*4]), &g_E2[r*576 + ch*32 + q*4]);
        }
        float* Bd = BS + buf*32*132;
        for (int i = tid; i < 1024; i += 256) {       // B: 32k x 32 f4 (4 bcl x 8)
            int k = i >> 5, j = i & 31;
            int bcl = j >> 3, q = j & 7;
            cp16(smem_u32(&Bd[k*132 + bcl*32 + q*4]),
                 &plane[(size_t)(bc0 + bcl)*XPLANE + (h0 + k)*32 + q*4]);
        }
    };

    float c[16][4];
    #pragma unroll
    for (int i = 0; i < 16; i++) { c[i][0]=0.f; c[i][1]=0.f; c[i][2]=0.f; c[i][3]=0.f; }

    stage(0, 0); CP_COMMIT();
    for (int ch = 0; ch < 18; ch++) {
        CP_WAIT_ALL();
        __syncthreads();
        if (ch + 1 < 18) { stage(ch + 1, (ch + 1) & 1); CP_COMMIT(); }
        const float* Ab = AS + (ch & 1)*128*36;
        const float* Bb = BS + (ch & 1)*32*132;
        #pragma unroll
        for (int ks = 0; ks < 4; ks++) {
            int kl = ks * 8;
            const float* Ar = &Ab[(warp*16 + g)*36 + kl + t];
            uint32_t a0 = __float_as_uint(Ar[0]);
            uint32_t a1 = __float_as_uint(Ar[8*36]);
            uint32_t a2 = __float_as_uint(Ar[4]);
            uint32_t a3 = __float_as_uint(Ar[8*36 + 4]);
            #pragma unroll
            for (int nt = 0; nt < 16; nt++) {
                uint32_t b0 = __float_as_uint(Bb[(kl + t)*132 + nt*8 + g]);
                uint32_t b1 = __float_as_uint(Bb[(kl + t + 4)*132 + nt*8 + g]);
                mma_tf32(c[nt], a0, a1, a2, a3, b0, b1);
            }
        }
        __syncthreads();
    }
    int m0 = warp * 16;
    float* P = (m0 < 64) ? g_Zr : g_Zi;
    int kx1 = (m0 & 63) + g, kx2 = kx1 + 8;
    #pragma unroll
    for (int nt = 0; nt < 16; nt++) {
        int col = nt*8 + 2*t;
        int bcl = col >> 5, kyc = col & 31;
        size_t b1 = (size_t)(bc0 + bcl)*ZPLANE + kx1*32 + kyc;
        size_t b2 = (size_t)(bc0 + bcl)*ZPLANE + kx2*32 + kyc;
        *(float2*)&P[b1] = make_float2(c[nt][0], c[nt][1]);
        *(float2*)&P[b2] = make_float2(c[nt][2], c[nt][3]);
    }
}

// ============ K3: per-mode channel mixing (fp32), writes tf32-rounded Yv ============
__global__ void k_modes(const float* __restrict__ spw1, const float* __restrict__ spw2) {
    int kx = blockIdx.x;
    int og = blockIdx.y;
    int ky = threadIdx.x & 31;
    int b  = threadIdx.x >> 5;
    const float* W; int mx;
    if (kx < 32) { W = spw1; mx = kx; } else { W = spw2; mx = kx - 32; }
    float yr[8], yi[8];
    #pragma unroll
    for (int oo = 0; oo < 8; oo++) { yr[oo] = 0.f; yi[oo] = 0.f; }
    for (int i = 0; i < CH; i++) {
        size_t zi_idx = (size_t)(b*CH + i)*ZPLANE + kx*32 + ky;
        float zr = g_Zr[zi_idx], zim = g_Zi[zi_idx];
        #pragma unroll
        for (int oo = 0; oo < 8; oo++) {
            int o = og*8 + oo;
            const float* wp = W + (((size_t)i*CH + o)*32 + mx)*32*2 + ky*2;
            float wr = wp[0], wi = wp[1];
            yr[oo] += zr*wr - zim*wi;
            yi[oo] += zr*wi + zim*wr;
        }
    }
    #pragma unroll
    for (int oo = 0; oo < 8; oo++) {
        int o = og*8 + oo;
        size_t idx = (size_t)(b*CH + o)*ZPLANE + kx*32 + ky;
        g_Yvr[idx] = to_tf32(yr[oo]);
        g_Yvi[idx] = to_tf32(yi[oo]);
    }
}

// ============ K4: inv H-DFT, batch 4 bo, cp.async pipelined A ============
// dyn smem: BS[128][132] + AS 2x[128][36] = 104448 B
__global__ void k4_idfth() {
    extern __shared__ float sm[];
    float* BS = sm;                 // [k=128][n=132], one-shot
    float* AS = sm + 128*132;       // 2 bufs 128*36
    int tid = threadIdx.x;
    int warp = tid >> 5, lane = tid & 31;
    int g = lane >> 2, t = lane & 3;
    int bog = blockIdx.x;
    int mt  = blockIdx.y;

    auto stageA = [&](int ch, int buf) {
        float* Ad = AS + buf*128*36;
        for (int i = tid; i < 1024; i += 256) {
            int r = i >> 3, q = i & 7;
            cp16(smem_u32(&Ad[r*36 + q*4]),
                 &g_I2[(size_t)(mt*128 + r)*128 + ch*32 + q*4]);
        }
    };
    // stage B (one-shot) + A(0)
    for (int i = tid; i < 4096; i += 256) {
        int k = i >> 5, j = i & 31;
        int bol = j >> 3, q = j & 7;
        const float* src = (k < 64)
            ? &g_Yvr[(size_t)(bog*4 + bol)*ZPLANE + k*32 + q*4]
            : &g_Yvi[(size_t)(bog*4 + bol)*ZPLANE + (k-64)*32 + q*4];
        cp16(smem_u32(&BS[k*132 + bol*32 + q*4]), src);
    }
    stageA(0, 0); CP_COMMIT();

    float c[16][4];
    #pragma unroll
    for (int i = 0; i < 16; i++) { c[i][0]=0.f; c[i][1]=0.f; c[i][2]=0.f; c[i][3]=0.f; }

    for (int ch = 0; ch < 4; ch++) {
        CP_WAIT_ALL();
        __syncthreads();
        if (ch + 1 < 4) { stageA(ch + 1, (ch + 1) & 1); CP_COMMIT(); }
        const float* Ab = AS + (ch & 1)*128*36;
        #pragma unroll
        for (int ks = 0; ks < 4; ks++) {
            int kl = ks * 8;
            const float* Ar = &Ab[(warp*16 + g)*36 + kl + t];
            uint32_t a0 = __float_as_uint(Ar[0]);
            uint32_t a1 = __float_as_uint(Ar[8*36]);
            uint32_t a2 = __float_as_uint(Ar[4]);
            uint32_t a3 = __float_as_uint(Ar[8*36 + 4]);
            int kg = ch*32 + kl;
            #pragma unroll
            for (int nt = 0; nt < 16; nt++) {
                uint32_t b0 = __float_as_uint(BS[(kg + t)*132 + nt*8 + g]);
                uint32_t b1 = __float_as_uint(BS[(kg + t + 4)*132 + nt*8 + g]);
                mma_tf32(c[nt], a0, a1, a2, a3, b0, b1);
            }
        }
        __syncthreads();
    }
    int R1 = mt*128 + warp*16 + g;
    int R2 = R1 + 8;
    #pragma unroll
    for (int nt = 0; nt < 16; nt++) {
        int col = nt*8 + 2*t;
        int bol = col >> 5, kyc = col & 31;
        if (R1 < 528) {
            int h = (R1 < 264) ? R1 : R1 - 264;
            float* P = (R1 < 264) ? g_Z2r : g_Z2i;
            *(float2*)&P[(size_t)(bog*4 + bol)*Z2PLANE + h*32 + kyc] =
                make_float2(to_tf32(c[nt][0]), to_tf32(c[nt][1]));
        }
        if (R2 < 528) {
            int h = (R2 < 264) ? R2 : R2 - 264;
            float* P = (R2 < 264) ? g_Z2r : g_Z2i;
            *(float2*)&P[(size_t)(bog*4 + bol)*Z2PLANE + h*32 + kyc] =
                make_float2(to_tf32(c[nt][2]), to_tf32(c[nt][3]));
        }
    }
}

// ============ K5 fused: conv GEMM + spectral invW GEMM + bias + gelu ============
// dyn smem: CW[64][68] + ZS[64][68] + HB[64][92] + WB[64][92] = 81920 B
__global__ void k5_fused(const float* __restrict__ hin,
                         const float* __restrict__ cw, const float* __restrict__ cb,
                         float* __restrict__ hout, int apply_gelu) {
    extern __shared__ float sm[];
    float* CW = sm;
    float* ZS = sm + 4352;
    float* HB = sm + 8704;
    float* WB = sm + 14592;
    int tid = threadIdx.x;
    int warp = tid >> 5, lane = tid & 31;
    int g = lane >> 2, t = lane & 3;
    int wt = blockIdx.x, h = blockIdx.y, b = blockIdx.z;
    int w0 = wt * 88;

    // ZS raw cp.async (pre-rounded Z2)
    for (int i = tid; i < 1024; i += 256) {
        int o = i >> 4, q = i & 15;
        int k4 = q * 4;
        const float* src = (k4 < 32)
            ? &g_Z2r[(size_t)(b*CH + o)*Z2PLANE + h*32 + k4]
            : &g_Z2i[(size_t)(b*CH + o)*Z2PLANE + h*32 + (k4 - 32)];
        cp16(smem_u32(&ZS[o*68 + k4]), src);
    }
    // HB / WB raw cp.async
    {
        int row = tid >> 2, tc = tid & 3;
        for (int q = tc; q < 22; q += 4) {
            cp16(smem_u32(&HB[row*92 + q*4]),
                 &hin[(size_t)(b*CH + row)*HW + (size_t)h*264 + w0 + q*4]);
            cp16(smem_u32(&WB[row*92 + q*4]), &g_K5B[row*264 + w0 + q*4]);
        }
    }
    CP_COMMIT();
    // CW regular (needs tf32 rounding of input weights)
    for (int i = tid; i < 1024; i += 256) {
        int o = i >> 4, q = i & 15;
        *(float4*)&CW[o*68 + q*4] = tf4(*(const float4*)&cw[o*64 + q*4]);
    }
    CP_WAIT_ALL();
    __syncthreads();

    int grp = warp >> 2;
    int m0 = (warp & 3) * 16;
    const float* Ab = grp ? ZS : CW;
    const float* Bb = grp ? WB : HB;

    float c[11][4];
    #pragma unroll
    for (int i = 0; i < 11; i++) { c[i][0]=0.f; c[i][1]=0.f; c[i][2]=0.f; c[i][3]=0.f; }

    #pragma unroll
    for (int ks = 0; ks < 8; ks++) {
        const float* Ar = &Ab[(m0 + g)*68 + ks*8 + t];
        uint32_t a0 = __float_as_uint(Ar[0]);
        uint32_t a1 = __float_as_uint(Ar[8*68]);
        uint32_t a2 = __float_as_uint(Ar[4]);
        uint32_t a3 = __float_as_uint(Ar[8*68 + 4]);
        #pragma unroll
        for (int nt = 0; nt < 11; nt++) {
            uint32_t b0 = __float_as_uint(Bb[(ks*8 + t)*92 + nt*8 + g]);
            uint32_t b1 = __float_as_uint(Bb[(ks*8 + t + 4)*92 + nt*8 + g]);
            mma_tf32(c[nt], a0, a1, a2, a3, b0, b1);
        }
    }
    __syncthreads();

    if (grp == 1) {
        #pragma unroll
        for (int nt = 0; nt < 11; nt++) {
            int col = nt*8 + 2*t;
            *(float2*)&WB[(m0 + g)*92 + col]     = make_float2(c[nt][0], c[nt][1]);
            *(float2*)&WB[(m0 + g + 8)*92 + col] = make_float2(c[nt][2], c[nt][3]);
        }
    }
    __syncthreads();

    if (grp == 0) {
        #pragma unroll
        for (int nt = 0; nt < 11; nt++) {
            int col = nt*8 + 2*t;
            #pragma unroll
            for (int half = 0; half < 2; half++) {
                int o = m0 + g + half*8;
                float2 sp = *(const float2*)&WB[o*92 + col];
                float bias = cb[o];
                float vx = c[nt][half*2 + 0] + sp.x + bias;
                float vy = c[nt][half*2 + 1] + sp.y + bias;
                if (apply_gelu) { vx = gelu_exact(vx); vy = gelu_exact(vy); }
                *(float2*)&hout[(size_t)(b*CH + o)*HW + (size_t)h*264 + w0 + col] =
                    make_float2(to_tf32(vx), to_tf32(vy));
            }
        }
    }
}

// ---------------- crop ----------------
__global__ void k_crop(const float* __restrict__ hin, float* __restrict__ out) {
    size_t idx = (size_t)blockIdx.x * blockDim.x + threadIdx.x;
    if (idx >= (size_t)BB*CH*H0*W0) return;
    int w  = (int)(idx & 255);
    int h  = (int)((idx >> 8) & 255);
    int bc = (int)(idx >> 16);
    out[idx] = hin[((size_t)bc*HP + h)*WP + w];
}

// ---------------- host launcher ----------------
extern "C" void kernel_launch(void* const* d_in, const int* in_sizes, int n_in,
                              void* d_out, int out_size) {
    const float* x       = (const float*)d_in[0];
    const float* lift_w1 = (const float*)d_in[1];
    const float* lift_b1 = (const float*)d_in[2];
    const float* lift_w2 = (const float*)d_in[3];
    const float* lift_b2 = (const float*)d_in[4];
    const float* conv_w  = (const float*)d_in[5];
    const float* conv_b  = (const float*)d_in[6];
    const float* spw1    = (const float*)d_in[7];
    const float* spw2    = (const float*)d_in[8];
    float* out = (float*)d_out;

    float *hA, *hB;
    cudaGetSymbolAddress((void**)&hA, g_hA);
    cudaGetSymbolAddress((void**)&hB, g_hB);

    const int K1_SMEM = (2*128*36 + 2*64*36) * 4;    // 55296
    const int K2_SMEM = (2*128*36 + 2*32*132) * 4;   // 70656
    const int K4_SMEM = (128*132 + 2*128*36) * 4;    // 104448
    const int K5_SMEM = (4352 + 4352 + 5888 + 5888) * 4; // 81920
    cudaFuncSetAttribute(k1_dftw,  cudaFuncAttributeMaxDynamicSharedMemorySize, K1_SMEM);
    cudaFuncSetAttribute(k2_dfth,  cudaFuncAttributeMaxDynamicSharedMemorySize, K2_SMEM);
    cudaFuncSetAttribute(k4_idfth, cudaFuncAttributeMaxDynamicSharedMemorySize, K4_SMEM);
    cudaFuncSetAttribute(k5_fused, cudaFuncAttributeMaxDynamicSharedMemorySize, K5_SMEM);

    k_init<<<(PAD_END + 255)/256, 256>>>();
    k_lift<<<dim3(HP, BB), 256>>>(x, lift_w1, lift_b1, lift_w2, lift_b2, hA);

    const size_t sp_stride = (size_t)CH*CH*32*32*2;
    for (int l = 0; l < NL; l++) {
        const float* hin  = (l & 1) ? hB : hA;
        float*       hnxt = (l & 1) ? hA : hB;
        k1_dftw<<<MROWS/128, 256, K1_SMEM>>>(hin);
        k2_dfth<<<128, 256, K2_SMEM>>>();
        k_modes<<<dim3(64, 8), 256>>>(spw1 + (size_t)l*sp_stride,
                                      spw2 + (size_t)l*sp_stride);
        k4_idfth<<<dim3(128, 5), 256, K4_SMEM>>>();
        k5_fused<<<dim3(3, HP, BB), 256, K5_SMEM>>>(hin,
                                                    conv_w + (size_t)l*CH*CH,
                                                    conv_b + (size_t)l*CH,
                                                    hnxt, (l < NL-1) ? 1 : 0);
    }
    k_crop<<<(int)(((size_t)BB*CH*H0*W0 + 255)/256), 256>>>(hA, out);
}

// round 10
// speedup vs baseline: 2.2732x; 1.0308x over previous
#include <cuda_runtime.h>
#include <math.h>
#include <stdint.h>

// ---------------- problem constants ----------------
#define BB   8
#define CIN  3
#define H0   256
#define W0   256
#define CH   64
#define MIDC 32
#define NL   4
#define HP   264
#define WP   264
#define HW   (HP*WP)          // 69696
#define MROWS (BB*CH*HP)      // 135168
#define XPLANE (288*32)
#define ZPLANE (64*32)
#define Z2PLANE (264*32)

// ---------------- scratch ----------------
__device__ __align__(16) float g_hA[(size_t)BB*CH*HW];
__device__ __align__(16) float g_hB[(size_t)BB*CH*HW];
__device__ __align__(16) float g_Xr[(size_t)512*XPLANE];
__device__ __align__(16) float g_Xi[(size_t)512*XPLANE];
__device__ __align__(16) float g_Zr[(size_t)512*ZPLANE];
__device__ __align__(16) float g_Zi[(size_t)512*ZPLANE];
__device__ __align__(16) float g_Yvr[(size_t)512*ZPLANE];
__device__ __align__(16) float g_Yvi[(size_t)512*ZPLANE];
__device__ __align__(16) float g_Z2r[(size_t)512*Z2PLANE];
__device__ __align__(16) float g_Z2i[(size_t)512*Z2PLANE];
__device__ __align__(16) float g_E2 [128*576];
__device__ __align__(16) float g_I2 [640*128];
__device__ __align__(16) float g_K1B[64*288];
__device__ __align__(16) float g_K5B[64*264];
__device__ __align__(16) float g_CW [64*64];     // per-layer tf32-rounded conv weights

__device__ __forceinline__ float gelu_exact(float v) {
    return 0.5f * v * (1.0f + erff(v * 0.70710678118654752f));
}
__device__ __forceinline__ float to_tf32(float x) {
    uint32_t u; asm("cvt.rna.tf32.f32 %0, %1;" : "=r"(u) : "f"(x));
    return __uint_as_float(u);
}
__device__ __forceinline__ void mma_tf32(float c[4], uint32_t a0, uint32_t a1,
                                         uint32_t a2, uint32_t a3,
                                         uint32_t b0, uint32_t b1) {
    asm volatile("mma.sync.aligned.m16n8k8.row.col.f32.tf32.tf32.f32 "
                 "{%0,%1,%2,%3},{%4,%5,%6,%7},{%8,%9},{%0,%1,%2,%3};"
                 : "+f"(c[0]), "+f"(c[1]), "+f"(c[2]), "+f"(c[3])
                 : "r"(a0), "r"(a1), "r"(a2), "r"(a3), "r"(b0), "r"(b1));
}
__device__ __forceinline__ uint32_t smem_u32(const void* p) {
    return (uint32_t)__cvta_generic_to_shared(p);
}
__device__ __forceinline__ void cp16(uint32_t dst, const void* src) {
    asm volatile("cp.async.cg.shared.global [%0], [%1], 16;" :: "r"(dst), "l"(src));
}
__device__ __forceinline__ void cp16z(uint32_t dst, const void* src, int bytes) {
    asm volatile("cp.async.cg.shared.global [%0], [%1], 16, %2;"
                 :: "r"(dst), "l"(src), "r"(bytes));
}
#define CP_COMMIT()   asm volatile("cp.async.commit_group;" ::: "memory")
#define CP_WAIT_ALL() asm volatile("cp.async.wait_group 0;" ::: "memory")

// ---------------- init: basis matrices + X pads ----------------
#define E2_END   73728
#define I2_END   155648
#define K1B_END  174080
#define K5B_END  190976
#define PAD_END  (190976 + 786432)

__global__ void k_init() {
    long long idx = (long long)blockIdx.x * blockDim.x + threadIdx.x;
    const double PI2 = 6.283185307179586476925286766559;
    if (idx < E2_END) {
        int r = (int)(idx / 576), k = (int)(idx % 576);
        int kx = r & 63; int kxv = (kx < 32) ? kx : kx + 200;
        int kp = (k < 288) ? k : k - 288;
        float v = 0.f;
        if (kp < 264) {
            double th = PI2 * (double)((kxv * kp) % 264) / 264.0;
            double c = cos(th), s = sin(th);
            if (k < 288) v = (float)((r < 64) ? c : -s);
            else         v = (float)((r < 64) ? s :  c);
        }
        g_E2[idx] = to_tf32(v);
    } else if (idx < I2_END) {
        int j = (int)(idx - E2_END);
        int R = j / 128, k = j % 128;
        float v = 0.f;
        if (R < 528) {
            int h = (R < 264) ? R : R - 264;
            int kx = k & 63; int kxv = (kx < 32) ? kx : kx + 200;
            double th = PI2 * (double)((kxv * h) % 264) / 264.0;
            double c = cos(th) / 264.0, s = sin(th) / 264.0;
            if (R < 264) v = (float)((k < 64) ? c : -s);
            else         v = (float)((k < 64) ? s :  c);
        }
        g_I2[j] = to_tf32(v);
    } else if (idx < K1B_END) {
        int j = (int)(idx - I2_END);
        int n = j / 288, k = j % 288;
        float v = 0.f;
        if (k < 264) {
            int ky = n >> 1;
            double th = PI2 * (double)((ky * k) % 264) / 264.0;
            v = (float)((n & 1) ? -sin(th) : cos(th));
        }
        g_K1B[j] = to_tf32(v);
    } else if (idx < K5B_END) {
        int j = (int)(idx - K1B_END);
        int k = j / 264, w = j % 264;
        int ky = k & 31;
        double wgt = ((ky == 0) ? 1.0 : 2.0) / 264.0;
        double th = PI2 * (double)((ky * w) % 264) / 264.0;
        double v = (k < 32) ? wgt * cos(th) : -wgt * sin(th);
        g_K5B[j] = to_tf32((float)v);
    } else if (idx < PAD_END) {
        long long j = idx - K5B_END;
        int ky = (int)(j & 31);
        int hh = (int)((j >> 5) % 24);
        long long rest = (j >> 5) / 24;
        int bc = (int)(rest & 511);
        int pl = (int)(rest >> 9);
        float* dst = pl ? g_Xi : g_Xr;
        dst[(size_t)bc * XPLANE + (264 + hh) * 32 + ky] = 0.f;
    }
}

// ---------------- per-layer conv weight pre-round ----------------
__global__ void k_prep(const float* __restrict__ cw) {
    int idx = blockIdx.x * blockDim.x + threadIdx.x;
    if (idx < 64*64) g_CW[idx] = to_tf32(cw[idx]);
}

// ---------------- lift (stores tf32-rounded activations) ----------------
__global__ void k_lift(const float* __restrict__ x,
                       const float* __restrict__ w1, const float* __restrict__ b1,
                       const float* __restrict__ w2, const float* __restrict__ b2,
                       float* __restrict__ hout) {
    int h = blockIdx.x, b = blockIdx.y;
    for (int w = threadIdx.x; w < WP; w += blockDim.x) {
        size_t base = ((size_t)b*CH)*HW + (size_t)h*WP + (size_t)w;
        if (h >= H0 || w >= W0) {
            for (int o = 0; o < CH; o++) hout[base + (size_t)o*HW] = 0.0f;
            continue;
        }
        float in5[5];
        #pragma unroll
        for (int c = 0; c < CIN; c++)
            in5[c] = x[(((size_t)b*CIN + c)*H0 + h)*W0 + w];
        in5[3] = (float)h * (1.0f/255.0f);
        in5[4] = (float)w * (1.0f/255.0f);
        float mid[MIDC];
        #pragma unroll
        for (int m = 0; m < MIDC; m++) {
            float s = b1[m];
            #pragma unroll
            for (int i = 0; i < 5; i++) s += w1[m*5 + i] * in5[i];
            mid[m] = gelu_exact(s);
        }
        #pragma unroll 8
        for (int o = 0; o < CH; o++) {
            float s = b2[o];
            #pragma unroll
            for (int m = 0; m < MIDC; m++) s += w2[o*MIDC + m] * mid[m];
            hout[base + (size_t)o*HW] = to_tf32(s);
        }
    }
}

// ============ K1: W-rDFT GEMM, M=256 per block, cp.async double-buffered ============
// dyn smem: AS 2x[256][36] + BS 2x[64][36] = 92160 B
__global__ __launch_bounds__(256, 2) void k1_dftw(const float* __restrict__ hin) {
    extern __shared__ float sm[];
    float* AS = sm;                 // 2 bufs 256*36
    float* BS = sm + 2*256*36;      // 2 bufs 64*36
    int tid = threadIdx.x;
    int warp = tid >> 5, lane = tid & 31;
    int g = lane >> 2, t = lane & 3;
    size_t row0 = (size_t)blockIdx.x * 256;

    auto stage = [&](int ch, int buf) {
        int k0 = ch * 32;
        float* Ad = AS + buf*256*36;
        for (int i = tid; i < 2048; i += 256) {       // A: 256 rows x 8 f4
            int r = i >> 3, q = i & 7;
            int k = k0 + q*4;
            const float* src = &hin[(row0 + r)*264 + ((k < 264) ? k : 0)];
            cp16z(smem_u32(&Ad[r*36 + q*4]), src, (k < 264) ? 16 : 0);
        }
        float* Bd = BS + buf*64*36;
        for (int i = tid; i < 512; i += 256) {        // B: 64 rows x 8 f4
            int n = i >> 3, q = i & 7;
            cp16(smem_u32(&Bd[n*36 + q*4]), &g_K1B[n*288 + k0 + q*4]);
        }
    };

    float c[2][8][4];
    #pragma unroll
    for (int m = 0; m < 2; m++)
        #pragma unroll
        for (int i = 0; i < 8; i++) { c[m][i][0]=0.f; c[m][i][1]=0.f; c[m][i][2]=0.f; c[m][i][3]=0.f; }

    stage(0, 0); CP_COMMIT();
    for (int ch = 0; ch < 9; ch++) {
        CP_WAIT_ALL();
        __syncthreads();
        if (ch + 1 < 9) { stage(ch + 1, (ch + 1) & 1); CP_COMMIT(); }
        const float* Ab = AS + (ch & 1)*256*36;
        const float* Bb = BS + (ch & 1)*64*36;
        #pragma unroll
        for (int ks = 0; ks < 4; ks++) {
            int kl = ks * 8;
            const float* Ar = &Ab[(warp*32 + g)*36 + kl + t];
            uint32_t a00 = __float_as_uint(Ar[0]);
            uint32_t a01 = __float_as_uint(Ar[8*36]);
            uint32_t a02 = __float_as_uint(Ar[4]);
            uint32_t a03 = __float_as_uint(Ar[8*36 + 4]);
            uint32_t a10 = __float_as_uint(Ar[16*36]);
            uint32_t a11 = __float_as_uint(Ar[24*36]);
            uint32_t a12 = __float_as_uint(Ar[16*36 + 4]);
            uint32_t a13 = __float_as_uint(Ar[24*36 + 4]);
            #pragma unroll
            for (int nt = 0; nt < 8; nt++) {
                uint32_t b0 = __float_as_uint(Bb[(nt*8 + g)*36 + kl + t]);
                uint32_t b1 = __float_as_uint(Bb[(nt*8 + g)*36 + kl + t + 4]);
                mma_tf32(c[0][nt], a00, a01, a02, a03, b0, b1);
                mma_tf32(c[1][nt], a10, a11, a12, a13, b0, b1);
            }
        }
        __syncthreads();
    }
    #pragma unroll
    for (int mt = 0; mt < 2; mt++) {
        int r1 = (int)row0 + warp*32 + mt*16 + g;
        int r2 = r1 + 8;
        int bc1 = r1 / 264, h1 = r1 % 264;
        int bc2 = r2 / 264, h2 = r2 % 264;
        size_t o1 = (size_t)bc1*XPLANE + h1*32;
        size_t o2 = (size_t)bc2*XPLANE + h2*32;
        #pragma unroll
        for (int nt = 0; nt < 8; nt++) {
            int ky = nt*4 + t;
            g_Xr[o1 + ky] = to_tf32(c[mt][nt][0]); g_Xi[o1 + ky] = to_tf32(c[mt][nt][1]);
            g_Xr[o2 + ky] = to_tf32(c[mt][nt][2]); g_Xi[o2 + ky] = to_tf32(c[mt][nt][3]);
        }
    }
}

// ============ K2: fwd H-DFT, batch 4 bc (N=128), cp.async double-buffered ============
// dyn smem: AS 2x[128][36] + BS 2x[32][132] = 70656 B
__global__ void k2_dfth() {
    extern __shared__ float sm[];
    float* AS = sm;                 // 2 bufs 128*36
    float* BS = sm + 2*128*36;      // 2 bufs 32*132
    int tid = threadIdx.x;
    int warp = tid >> 5, lane = tid & 31;
    int g = lane >> 2, t = lane & 3;
    int bc0 = blockIdx.x * 4;

    auto stage = [&](int ch, int buf) {
        const float* plane = (ch < 9) ? g_Xr : g_Xi;
        int h0 = ((ch < 9) ? ch : ch - 9) * 32;
        float* Ad = AS + buf*128*36;
        for (int i = tid; i < 1024; i += 256) {
            int r = i >> 3, q = i & 7;
            cp16(smem_u32(&Ad[r*36 + q*4]), &g_E2[r*576 + ch*32 + q*4]);
        }
        float* Bd = BS + buf*32*132;
        for (int i = tid; i < 1024; i += 256) {
            int k = i >> 5, j = i & 31;
            int bcl = j >> 3, q = j & 7;
            cp16(smem_u32(&Bd[k*132 + bcl*32 + q*4]),
                 &plane[(size_t)(bc0 + bcl)*XPLANE + (h0 + k)*32 + q*4]);
        }
    };

    float c[16][4];
    #pragma unroll
    for (int i = 0; i < 16; i++) { c[i][0]=0.f; c[i][1]=0.f; c[i][2]=0.f; c[i][3]=0.f; }

    stage(0, 0); CP_COMMIT();
    for (int ch = 0; ch < 18; ch++) {
        CP_WAIT_ALL();
        __syncthreads();
        if (ch + 1 < 18) { stage(ch + 1, (ch + 1) & 1); CP_COMMIT(); }
        const float* Ab = AS + (ch & 1)*128*36;
        const float* Bb = BS + (ch & 1)*32*132;
        #pragma unroll
        for (int ks = 0; ks < 4; ks++) {
            int kl = ks * 8;
            const float* Ar = &Ab[(warp*16 + g)*36 + kl + t];
            uint32_t a0 = __float_as_uint(Ar[0]);
            uint32_t a1 = __float_as_uint(Ar[8*36]);
            uint32_t a2 = __float_as_uint(Ar[4]);
            uint32_t a3 = __float_as_uint(Ar[8*36 + 4]);
            #pragma unroll
            for (int nt = 0; nt < 16; nt++) {
                uint32_t b0 = __float_as_uint(Bb[(kl + t)*132 + nt*8 + g]);
                uint32_t b1 = __float_as_uint(Bb[(kl + t + 4)*132 + nt*8 + g]);
                mma_tf32(c[nt], a0, a1, a2, a3, b0, b1);
            }
        }
        __syncthreads();
    }
    int m0 = warp * 16;
    float* P = (m0 < 64) ? g_Zr : g_Zi;
    int kx1 = (m0 & 63) + g, kx2 = kx1 + 8;
    #pragma unroll
    for (int nt = 0; nt < 16; nt++) {
        int col = nt*8 + 2*t;
        int bcl = col >> 5, kyc = col & 31;
        size_t b1 = (size_t)(bc0 + bcl)*ZPLANE + kx1*32 + kyc;
        size_t b2 = (size_t)(bc0 + bcl)*ZPLANE + kx2*32 + kyc;
        *(float2*)&P[b1] = make_float2(c[nt][0], c[nt][1]);
        *(float2*)&P[b2] = make_float2(c[nt][2], c[nt][3]);
    }
}

// ============ K3: per-mode channel mixing (fp32), writes tf32-rounded Yv ============
__global__ void k_modes(const float* __restrict__ spw1, const float* __restrict__ spw2) {
    int kx = blockIdx.x;
    int og = blockIdx.y;
    int ky = threadIdx.x & 31;
    int b  = threadIdx.x >> 5;
    const float* W; int mx;
    if (kx < 32) { W = spw1; mx = kx; } else { W = spw2; mx = kx - 32; }
    float yr[8], yi[8];
    #pragma unroll
    for (int oo = 0; oo < 8; oo++) { yr[oo] = 0.f; yi[oo] = 0.f; }
    for (int i = 0; i < CH; i++) {
        size_t zi_idx = (size_t)(b*CH + i)*ZPLANE + kx*32 + ky;
        float zr = g_Zr[zi_idx], zim = g_Zi[zi_idx];
        #pragma unroll
        for (int oo = 0; oo < 8; oo++) {
            int o = og*8 + oo;
            const float* wp = W + (((size_t)i*CH + o)*32 + mx)*32*2 + ky*2;
            float wr = wp[0], wi = wp[1];
            yr[oo] += zr*wr - zim*wi;
            yi[oo] += zr*wi + zim*wr;
        }
    }
    #pragma unroll
    for (int oo = 0; oo < 8; oo++) {
        int o = og*8 + oo;
        size_t idx = (size_t)(b*CH + o)*ZPLANE + kx*32 + ky;
        g_Yvr[idx] = to_tf32(yr[oo]);
        g_Yvi[idx] = to_tf32(yi[oo]);
    }
}

// ============ K4: inv H-DFT, batch 2 bo (2 blocks/SM), cp.async pipelined A ============
// dyn smem: BS[128][68] + AS 2x[128][36] = 71680 B
__global__ __launch_bounds__(256, 2) void k4_idfth() {
    extern __shared__ float sm[];
    float* BS = sm;                 // [k=128][n=68], one-shot (2 bo x 32 ky)
    float* AS = sm + 128*68;        // 2 bufs 128*36
    int tid = threadIdx.x;
    int warp = tid >> 5, lane = tid & 31;
    int g = lane >> 2, t = lane & 3;
    int bog = blockIdx.x;           // 0..255, bo pair base bog*2
    int mt  = blockIdx.y;

    auto stageA = [&](int ch, int buf) {
        float* Ad = AS + buf*128*36;
        for (int i = tid; i < 1024; i += 256) {
            int r = i >> 3, q = i & 7;
            cp16(smem_u32(&Ad[r*36 + q*4]),
                 &g_I2[(size_t)(mt*128 + r)*128 + ch*32 + q*4]);
        }
    };
    // stage B (one-shot): 128 k x 64 n  -> 128x16 f4
    for (int i = tid; i < 2048; i += 256) {
        int k = i >> 4, j = i & 15;
        int bol = j >> 3, q = j & 7;
        const float* src = (k < 64)
            ? &g_Yvr[(size_t)(bog*2 + bol)*ZPLANE + k*32 + q*4]
            : &g_Yvi[(size_t)(bog*2 + bol)*ZPLANE + (k-64)*32 + q*4];
        cp16(smem_u32(&BS[k*68 + bol*32 + q*4]), src);
    }
    stageA(0, 0); CP_COMMIT();

    float c[8][4];
    #pragma unroll
    for (int i = 0; i < 8; i++) { c[i][0]=0.f; c[i][1]=0.f; c[i][2]=0.f; c[i][3]=0.f; }

    for (int ch = 0; ch < 4; ch++) {
        CP_WAIT_ALL();
        __syncthreads();
        if (ch + 1 < 4) { stageA(ch + 1, (ch + 1) & 1); CP_COMMIT(); }
        const float* Ab = AS + (ch & 1)*128*36;
        #pragma unroll
        for (int ks = 0; ks < 4; ks++) {
            int kl = ks * 8;
            const float* Ar = &Ab[(warp*16 + g)*36 + kl + t];
            uint32_t a0 = __float_as_uint(Ar[0]);
            uint32_t a1 = __float_as_uint(Ar[8*36]);
            uint32_t a2 = __float_as_uint(Ar[4]);
            uint32_t a3 = __float_as_uint(Ar[8*36 + 4]);
            int kg = ch*32 + kl;
            #pragma unroll
            for (int nt = 0; nt < 8; nt++) {
                uint32_t b0 = __float_as_uint(BS[(kg + t)*68 + nt*8 + g]);
                uint32_t b1 = __float_as_uint(BS[(kg + t + 4)*68 + nt*8 + g]);
                mma_tf32(c[nt], a0, a1, a2, a3, b0, b1);
            }
        }
        __syncthreads();
    }
    int R1 = mt*128 + warp*16 + g;
    int R2 = R1 + 8;
    #pragma unroll
    for (int nt = 0; nt < 8; nt++) {
        int col = nt*8 + 2*t;
        int bol = col >> 5, kyc = col & 31;
        if (R1 < 528) {
            int h = (R1 < 264) ? R1 : R1 - 264;
            float* P = (R1 < 264) ? g_Z2r : g_Z2i;
            *(float2*)&P[(size_t)(bog*2 + bol)*Z2PLANE + h*32 + kyc] =
                make_float2(to_tf32(c[nt][0]), to_tf32(c[nt][1]));
        }
        if (R2 < 528) {
            int h = (R2 < 264) ? R2 : R2 - 264;
            float* P = (R2 < 264) ? g_Z2r : g_Z2i;
            *(float2*)&P[(size_t)(bog*2 + bol)*Z2PLANE + h*32 + kyc] =
                make_float2(to_tf32(c[nt][2]), to_tf32(c[nt][3]));
        }
    }
}

// ============ K5 fused: conv GEMM + spectral invW GEMM + bias + gelu ============
// dyn smem: CW[64][68] + ZS[64][68] + HB[64][100] + WB[64][100] = 86016 B
__global__ __launch_bounds__(256, 2) void k5_fused(const float* __restrict__ hin,
                         const float* __restrict__ cb,
                         float* __restrict__ hout, int apply_gelu) {
    extern __shared__ float sm[];
    float* CW = sm;                 // 64*68
    float* ZS = sm + 4352;          // 64*68
    float* HB = sm + 8704;          // 64*100
    float* WB = sm + 15104;         // 64*100 (spectral B, then spill)
    int tid = threadIdx.x;
    int warp = tid >> 5, lane = tid & 31;
    int g = lane >> 2, t = lane & 3;
    int wt = blockIdx.x, h = blockIdx.y, b = blockIdx.z;
    int w0 = wt * 88;

    // CW + ZS raw cp.async (both pre-rounded)
    for (int i = tid; i < 1024; i += 256) {
        int o = i >> 4, q = i & 15;
        int k4 = q * 4;
        cp16(smem_u32(&CW[o*68 + k4]), &g_CW[o*64 + k4]);
        const float* src = (k4 < 32)
            ? &g_Z2r[(size_t)(b*CH + o)*Z2PLANE + h*32 + k4]
            : &g_Z2i[(size_t)(b*CH + o)*Z2PLANE + h*32 + (k4 - 32)];
        cp16(smem_u32(&ZS[o*68 + k4]), src);
    }
    // HB / WB raw cp.async
    {
        int row = tid >> 2, tc = tid & 3;
        for (int q = tc; q < 22; q += 4) {
            cp16(smem_u32(&HB[row*100 + q*4]),
                 &hin[(size_t)(b*CH + row)*HW + (size_t)h*264 + w0 + q*4]);
            cp16(smem_u32(&WB[row*100 + q*4]), &g_K5B[row*264 + w0 + q*4]);
        }
    }
    CP_COMMIT();
    CP_WAIT_ALL();
    __syncthreads();

    int grp = warp >> 2;
    int m0 = (warp & 3) * 16;
    const float* Ab = grp ? ZS : CW;
    const float* Bb = grp ? WB : HB;

    float c[11][4];
    #pragma unroll
    for (int i = 0; i < 11; i++) { c[i][0]=0.f; c[i][1]=0.f; c[i][2]=0.f; c[i][3]=0.f; }

    #pragma unroll
    for (int ks = 0; ks < 8; ks++) {
        const float* Ar = &Ab[(m0 + g)*68 + ks*8 + t];
        uint32_t a0 = __float_as_uint(Ar[0]);
        uint32_t a1 = __float_as_uint(Ar[8*68]);
        uint32_t a2 = __float_as_uint(Ar[4]);
        uint32_t a3 = __float_as_uint(Ar[8*68 + 4]);
        #pragma unroll
        for (int nt = 0; nt < 11; nt++) {
            uint32_t b0 = __float_as_uint(Bb[(ks*8 + t)*100 + nt*8 + g]);
            uint32_t b1 = __float_as_uint(Bb[(ks*8 + t + 4)*100 + nt*8 + g]);
            mma_tf32(c[nt], a0, a1, a2, a3, b0, b1);
        }
    }
    __syncthreads();

    if (grp == 1) {
        #pragma unroll
        for (int nt = 0; nt < 11; nt++) {
            int col = nt*8 + 2*t;
            *(float2*)&WB[(m0 + g)*100 + col]     = make_float2(c[nt][0], c[nt][1]);
            *(float2*)&WB[(m0 + g + 8)*100 + col] = make_float2(c[nt][2], c[nt][3]);
        }
    }
    __syncthreads();

    if (grp == 0) {
        #pragma unroll
        for (int nt = 0; nt < 11; nt++) {
            int col = nt*8 + 2*t;
            #pragma unroll
            for (int half = 0; half < 2; half++) {
                int o = m0 + g + half*8;
                float2 sp = *(const float2*)&WB[o*100 + col];
                float bias = cb[o];
                float vx = c[nt][half*2 + 0] + sp.x + bias;
                float vy = c[nt][half*2 + 1] + sp.y + bias;
                if (apply_gelu) { vx = gelu_exact(vx); vy = gelu_exact(vy); }
                *(float2*)&hout[(size_t)(b*CH + o)*HW + (size_t)h*264 + w0 + col] =
                    make_float2(to_tf32(vx), to_tf32(vy));
            }
        }
    }
}

// ---------------- crop ----------------
__global__ void k_crop(const float* __restrict__ hin, float* __restrict__ out) {
    size_t idx = (size_t)blockIdx.x * blockDim.x + threadIdx.x;
    if (idx >= (size_t)BB*CH*H0*W0) return;
    int w  = (int)(idx & 255);
    int h  = (int)((idx >> 8) & 255);
    int bc = (int)(idx >> 16);
    out[idx] = hin[((size_t)bc*HP + h)*WP + w];
}

// ---------------- host launcher ----------------
extern "C" void kernel_launch(void* const* d_in, const int* in_sizes, int n_in,
                              void* d_out, int out_size) {
    const float* x       = (const float*)d_in[0];
    const float* lift_w1 = (const float*)d_in[1];
    const float* lift_b1 = (const float*)d_in[2];
    const float* lift_w2 = (const float*)d_in[3];
    const float* lift_b2 = (const float*)d_in[4];
    const float* conv_w  = (const float*)d_in[5];
    const float* conv_b  = (const float*)d_in[6];
    const float* spw1    = (const float*)d_in[7];
    const float* spw2    = (const float*)d_in[8];
    float* out = (float*)d_out;

    float *hA, *hB;
    cudaGetSymbolAddress((void**)&hA, g_hA);
    cudaGetSymbolAddress((void**)&hB, g_hB);

    const int K1_SMEM = (2*256*36 + 2*64*36) * 4;    // 92160
    const int K2_SMEM = (2*128*36 + 2*32*132) * 4;   // 70656
    const int K4_SMEM = (128*68 + 2*128*36) * 4;     // 71680
    const int K5_SMEM = (4352 + 4352 + 6400 + 6400) * 4; // 86016
    cudaFuncSetAttribute(k1_dftw,  cudaFuncAttributeMaxDynamicSharedMemorySize, K1_SMEM);
    cudaFuncSetAttribute(k2_dfth,  cudaFuncAttributeMaxDynamicSharedMemorySize, K2_SMEM);
    cudaFuncSetAttribute(k4_idfth, cudaFuncAttributeMaxDynamicSharedMemorySize, K4_SMEM);
    cudaFuncSetAttribute(k5_fused, cudaFuncAttributeMaxDynamicSharedMemorySize, K5_SMEM);

    k_init<<<(PAD_END + 255)/256, 256>>>();
    k_lift<<<dim3(HP, BB), 256>>>(x, lift_w1, lift_b1, lift_w2, lift_b2, hA);

    const size_t sp_stride = (size_t)CH*CH*32*32*2;
    for (int l = 0; l < NL; l++) {
        const float* hin  = (l & 1) ? hB : hA;
        float*       hnxt = (l & 1) ? hA : hB;
        k_prep<<<16, 256>>>(conv_w + (size_t)l*CH*CH);
        k1_dftw<<<MROWS/256, 256, K1_SMEM>>>(hin);
        k2_dfth<<<128, 256, K2_SMEM>>>();
        k_modes<<<dim3(64, 8), 256>>>(spw1 + (size_t)l*sp_stride,
                                      spw2 + (size_t)l*sp_stride);
        k4_idfth<<<dim3(256, 5), 256, K4_SMEM>>>();
        k5_fused<<<dim3(3, HP, BB), 256, K5_SMEM>>>(hin,
                                                    conv_b + (size_t)l*CH,
                                                    hnxt, (l < NL-1) ? 1 : 0);
    }
    k_crop<<<(int)(((size_t)BB*CH*H0*W0 + 255)/256), 256>>>(hA, out);
}